// round 10
// baseline (speedup 1.0000x reference)
#include <cuda_runtime.h>
#include <math.h>
#include <stdint.h>

// ---------------- problem constants ----------------
#define Bc    4
#define Tt    4
#define Hh    128
#define Wd    128
#define D     384
#define DEPTH 4
#define DIN   768
#define Nst   16
#define DTR   24
#define NTOK  256
#define Lseq  257
#define POS   128
#define XDBE  56          // DTR + 2N
#define GWp   8           // W/P
#define MSEQ  (Bc*Lseq)   // 1028

// ---------------- scratch (device globals; no allocation allowed) ----------------
__device__ float g_xr[Bc*NTOK*256];
__device__ float g_tok[Bc*NTOK*D];
__device__ float g_resid[Bc*Lseq*D];
__device__ float g_hidden[Bc*Lseq*D];
__device__ float g_hn[Bc*Lseq*D];
__device__ float g_xz[Bc*Lseq*2*DIN];
__device__ float g_xc[2][Bc*Lseq*DIN];
__device__ float g_xdb[2][Bc*Lseq*XDBE];
__device__ float g_dt[2][Bc*Lseq*DIN];
__device__ float g_y[2][Bc*Lseq*DIN];

__device__ __forceinline__ float silu_f(float v) {
    return v / (1.0f + __expf(-v));
}

__device__ __forceinline__ uint32_t f2tf32(float v) {
    uint32_t o;
    asm("cvt.rna.tf32.f32 %0, %1;" : "=r"(o) : "f"(v));
    return o;
}

__device__ __forceinline__ void mma_tf32(float* c, const uint32_t* a, const uint32_t* b) {
    asm volatile(
        "mma.sync.aligned.m16n8k8.row.col.f32.tf32.tf32.f32 "
        "{%0,%1,%2,%3}, {%4,%5,%6,%7}, {%8,%9}, {%0,%1,%2,%3};"
        : "+f"(c[0]), "+f"(c[1]), "+f"(c[2]), "+f"(c[3])
        : "r"(a[0]), "r"(a[1]), "r"(a[2]), "r"(a[3]),
          "r"(b[0]), "r"(b[1]));
}

// ---------------- patchify: depth_seq -> xr; also zero g_tok (split-K target) ----------------
__global__ void patchify_kernel(const float* __restrict__ depth) {
    int idx = blockIdx.x * blockDim.x + threadIdx.x;
    int nthr = gridDim.x * blockDim.x;
    for (int i = idx; i < Bc*NTOK*D; i += nthr) g_tok[i] = 0.0f;
    if (idx >= Bc*NTOK*256) return;
    int j   = idx & 255;
    int tok = (idx >> 8) % NTOK;
    int b   = idx / (256*NTOK);
    int p2 = j & 15, p1 = j >> 4;
    int gw = tok % GWp, gh = tok / GWp;
    int y = gh*16 + p1, x = gw*16 + p2;
    g_xr[idx] = depth[((long)b*(Tt*Hh) + y)*Wd + x];
}

// ============ tensor-core tf32 GEMM: C (+)= act((A[m] + A2flip[flip(m)]) @ W^T + bias) ============
// 128x64 block tile, BK=16, 256 threads = 8 warps in a 4x2 quad grid, warp tile 32x32.
// Permuted smem layout within each 8-k chunk: pos = (k%4)*2 + k/4  => lane's (k, k+4) pair
// is a contiguous float2.
// ksplit > 1: grid.z = Zbr*ksplit, each slice covers K/ksplit k-tiles, epilogue atomicAdd
// (no bias/act on that path).
#define GSTR 18     // 16 + 2 pad (floats)

__global__ __launch_bounds__(256, 3) void mma_gemm_kernel(
    const float* __restrict__ A, const float* __restrict__ A2flip,
    const float* __restrict__ W0, const float* __restrict__ W1,
    const float* __restrict__ bias0, const float* __restrict__ bias1,
    float* __restrict__ C,
    int M, int N, int K, int lda, int ldc,
    long strideA, long strideC, int act, int ksplit)
{
    __shared__ float As[2][128][GSTR];
    __shared__ float Ws[2][64][GSTR];

    int z = blockIdx.z;
    int br = z / ksplit;
    int ks = z - br * ksplit;

    const float* Ap = A + (long)br * strideA;
    const float* Wp = br ? W1 : W0;
    const float* bp = br ? bias1 : bias0;
    float* Cp = C + (long)br * strideC;

    int tid  = threadIdx.x;
    int warp = tid >> 5, lane = tid & 31;
    int wm = warp >> 1, wn = warp & 1;          // 4 x 2 quads
    int qr = lane >> 2, qc = lane & 3;
    int m0 = blockIdx.y * 128, n0 = blockIdx.x * 64;

    // staging: thread stages two A float4 (rows srow, srow+64) and one W float4 (row srow)
    int srow = tid >> 2;           // 0..63
    int sc4  = (tid & 3) * 4;      // 0,4,8,12
    int spos = ((sc4 >> 3) << 3) + ((sc4 >> 2) & 1);   // permuted base, stride 2

    int amA0 = m0 + srow, amA1 = m0 + srow + 64;
    bool a0ok = (amA0 < M), a1ok = (amA1 < M);
    long aoff0 = (long)amA0 * lda, aoff1 = (long)amA1 * lda;
    long a2off0 = 0, a2off1 = 0;
    if (A2flip) {
        int b0 = amA0 / Lseq, l0 = amA0 % Lseq;
        a2off0 = ((long)b0 * Lseq + (Lseq - 1 - l0)) * lda;
        int b1 = amA1 / Lseq, l1 = amA1 % Lseq;
        a2off1 = ((long)b1 * Lseq + (Lseq - 1 - l1)) * lda;
    }
    int wrow = n0 + srow;
    bool wok = (wrow < N);
    long woff = (long)wrow * K;

    float acc[2][4][4];
    #pragma unroll
    for (int i = 0; i < 2; i++)
        #pragma unroll
        for (int j = 0; j < 4; j++)
            #pragma unroll
            for (int q = 0; q < 4; q++) acc[i][j][q] = 0.0f;

    int nk_total = (K + 15) / 16;
    int nk_s = nk_total / ksplit;
    int kt0 = ks * nk_s, kt1 = kt0 + nk_s;

    const float4 zero4 = make_float4(0.f, 0.f, 0.f, 0.f);
    float4 ra0, ra1, rw;

    // hoisted fragment base pointers (per buffer)
    const float* paB[2] = { &As[0][wm*32 + qr][qc*2], &As[1][wm*32 + qr][qc*2] };
    const float* pwB[2] = { &Ws[0][wn*32 + qr][qc*2], &Ws[1][wn*32 + qr][qc*2] };

    // ---- prologue: load tile kt0 ----
    {
        int k = kt0 * 16 + sc4;
        bool kok = (k < K);
        ra0 = (a0ok && kok) ? *(const float4*)(Ap + aoff0 + k) : zero4;
        ra1 = (a1ok && kok) ? *(const float4*)(Ap + aoff1 + k) : zero4;
        if (A2flip && kok) {
            if (a0ok) { float4 t = *(const float4*)(A2flip + a2off0 + k);
                ra0.x += t.x; ra0.y += t.y; ra0.z += t.z; ra0.w += t.w; }
            if (a1ok) { float4 t = *(const float4*)(A2flip + a2off1 + k);
                ra1.x += t.x; ra1.y += t.y; ra1.z += t.z; ra1.w += t.w; }
        }
        rw = (wok && kok) ? *(const float4*)(Wp + woff + k) : zero4;
    }
    {
        float* p0 = &As[0][srow][spos];
        p0[0] = __uint_as_float(f2tf32(ra0.x)); p0[2] = __uint_as_float(f2tf32(ra0.y));
        p0[4] = __uint_as_float(f2tf32(ra0.z)); p0[6] = __uint_as_float(f2tf32(ra0.w));
        float* p1 = &As[0][srow + 64][spos];
        p1[0] = __uint_as_float(f2tf32(ra1.x)); p1[2] = __uint_as_float(f2tf32(ra1.y));
        p1[4] = __uint_as_float(f2tf32(ra1.z)); p1[6] = __uint_as_float(f2tf32(ra1.w));
        float* pw = &Ws[0][srow][spos];
        pw[0] = __uint_as_float(f2tf32(rw.x)); pw[2] = __uint_as_float(f2tf32(rw.y));
        pw[4] = __uint_as_float(f2tf32(rw.z)); pw[6] = __uint_as_float(f2tf32(rw.w));
    }
    __syncthreads();

    for (int kt = kt0; kt < kt1; kt++) {
        int cur = (kt - kt0) & 1;
        if (kt + 1 < kt1) {
            int k = (kt + 1) * 16 + sc4;
            bool kok = (k < K);
            ra0 = (a0ok && kok) ? *(const float4*)(Ap + aoff0 + k) : zero4;
            ra1 = (a1ok && kok) ? *(const float4*)(Ap + aoff1 + k) : zero4;
            if (A2flip && kok) {
                if (a0ok) { float4 t = *(const float4*)(A2flip + a2off0 + k);
                    ra0.x += t.x; ra0.y += t.y; ra0.z += t.z; ra0.w += t.w; }
                if (a1ok) { float4 t = *(const float4*)(A2flip + a2off1 + k);
                    ra1.x += t.x; ra1.y += t.y; ra1.z += t.z; ra1.w += t.w; }
            }
            rw = (wok && kok) ? *(const float4*)(Wp + woff + k) : zero4;
        }
        // ---- compute tile cur: 2 chunks of 8 k ----
        #pragma unroll
        for (int kk = 0; kk < 2; kk++) {
            int co = kk * 8;
            uint32_t afr[2][4];
            #pragma unroll
            for (int fm = 0; fm < 2; fm++) {
                const float* pa = paB[cur] + fm*16*GSTR + co;
                float2 lo = *(const float2*)pa;
                float2 hi = *(const float2*)(pa + 8*GSTR);
                afr[fm][0] = __float_as_uint(lo.x);
                afr[fm][1] = __float_as_uint(hi.x);
                afr[fm][2] = __float_as_uint(lo.y);
                afr[fm][3] = __float_as_uint(hi.y);
            }
            uint32_t bfr[4][2];
            #pragma unroll
            for (int fn = 0; fn < 4; fn++) {
                float2 bb = *(const float2*)(pwB[cur] + fn*8*GSTR + co);
                bfr[fn][0] = __float_as_uint(bb.x);
                bfr[fn][1] = __float_as_uint(bb.y);
            }
            #pragma unroll
            for (int fm = 0; fm < 2; fm++)
                #pragma unroll
                for (int fn = 0; fn < 4; fn++)
                    mma_tf32(acc[fm][fn], afr[fm], bfr[fn]);
        }
        if (kt + 1 < kt1) {
            int nxt = (kt + 1 - kt0) & 1;
            float* p0 = &As[nxt][srow][spos];
            p0[0] = __uint_as_float(f2tf32(ra0.x)); p0[2] = __uint_as_float(f2tf32(ra0.y));
            p0[4] = __uint_as_float(f2tf32(ra0.z)); p0[6] = __uint_as_float(f2tf32(ra0.w));
            float* p1 = &As[nxt][srow + 64][spos];
            p1[0] = __uint_as_float(f2tf32(ra1.x)); p1[2] = __uint_as_float(f2tf32(ra1.y));
            p1[4] = __uint_as_float(f2tf32(ra1.z)); p1[6] = __uint_as_float(f2tf32(ra1.w));
            float* pw = &Ws[nxt][srow][spos];
            pw[0] = __uint_as_float(f2tf32(rw.x)); pw[2] = __uint_as_float(f2tf32(rw.y));
            pw[4] = __uint_as_float(f2tf32(rw.z)); pw[6] = __uint_as_float(f2tf32(rw.w));
            __syncthreads();
        }
    }

    // ---- epilogue ----
    bool do_atomic = (ksplit > 1);
    #pragma unroll
    for (int fm = 0; fm < 2; fm++) {
        #pragma unroll
        for (int fn = 0; fn < 4; fn++) {
            #pragma unroll
            for (int half = 0; half < 2; half++) {
                int m = m0 + wm*32 + fm*16 + qr + half*8;
                int ncol = n0 + wn*32 + fn*8 + qc*2;
                if (m >= M || ncol >= N) continue;
                float v0 = acc[fm][fn][half*2];
                float v1 = acc[fm][fn][half*2 + 1];
                if (do_atomic) {
                    atomicAdd(Cp + (long)m*ldc + ncol,     v0);
                    atomicAdd(Cp + (long)m*ldc + ncol + 1, v1);
                } else {
                    if (bp) { v0 += bp[ncol]; v1 += bp[ncol + 1]; }
                    if (act == 2) {
                        v0 = (v0 > 15.0f) ? v0 : log1pf(__expf(v0));
                        v1 = (v1 > 15.0f) ? v1 : log1pf(__expf(v1));
                    }
                    *(float2*)(Cp + (long)m*ldc + ncol) = make_float2(v0, v1);
                }
            }
        }
    }
}

// ---------------- residual accumulate + layernorm: warp per row, float4 ----------------
__global__ void resln_kernel(const float* __restrict__ lw, const float* __restrict__ lb,
                             const float* __restrict__ cls, const float* __restrict__ pos,
                             int first) {
    int row = blockIdx.x * 4 + (threadIdx.x >> 5);
    if (row >= MSEQ) return;
    int lane = threadIdx.x & 31;
    long base = (long)row * D;

    float4 v[3];
    float s = 0.f, q = 0.f;
    if (first) {
        int b = row / Lseq, l = row % Lseq;
        const float* src;
        if (l < POS)       src = g_tok + ((long)b*NTOK + l)*D;
        else if (l == POS) src = cls;
        else               src = g_tok + ((long)b*NTOK + l - 1)*D;
        #pragma unroll
        for (int j = 0; j < 3; j++) {
            int d0 = (lane + j*32) * 4;
            float4 t = *(const float4*)(src + d0);
            float4 pe = *(const float4*)(pos + (long)l*D + d0);
            t.x += pe.x; t.y += pe.y; t.z += pe.z; t.w += pe.w;
            v[j] = t;
            s += t.x + t.y + t.z + t.w;
            q += t.x*t.x + t.y*t.y + t.z*t.z + t.w*t.w;
        }
    } else {
        #pragma unroll
        for (int j = 0; j < 3; j++) {
            int d0 = (lane + j*32) * 4;
            float4 t = *(const float4*)(&g_hidden[base + d0]);
            float4 r = *(const float4*)(&g_resid[base + d0]);
            t.x += r.x; t.y += r.y; t.z += r.z; t.w += r.w;
            v[j] = t;
            s += t.x + t.y + t.z + t.w;
            q += t.x*t.x + t.y*t.y + t.z*t.z + t.w*t.w;
        }
    }
    #pragma unroll
    for (int o = 16; o > 0; o >>= 1) {
        s += __shfl_xor_sync(~0u, s, o);
        q += __shfl_xor_sync(~0u, q, o);
    }
    float mean = s / D;
    float rstd = rsqrtf(q / D - mean*mean + 1e-5f);
    #pragma unroll
    for (int j = 0; j < 3; j++) {
        int d0 = (lane + j*32) * 4;
        *(float4*)(&g_resid[base + d0]) = v[j];
        float4 wv = *(const float4*)(lw + d0);
        float4 bv = *(const float4*)(lb + d0);
        float4 o;
        o.x = (v[j].x - mean)*rstd*wv.x + bv.x;
        o.y = (v[j].y - mean)*rstd*wv.y + bv.y;
        o.z = (v[j].z - mean)*rstd*wv.z + bv.z;
        o.w = (v[j].w - mean)*rstd*wv.w + bv.w;
        *(float4*)(&g_hn[base + d0]) = o;
    }
}

// ---------------- causal conv (K=4) + silu, both branches (float4) ----------------
// Also zeroes the split-K accumulation targets: g_xdb row (per br) and g_hidden row (br==0).
__global__ void conv_kernel(const float* __restrict__ cw,  const float* __restrict__ cb,
                            const float* __restrict__ cwb, const float* __restrict__ cbb)
{
    int row = blockIdx.x;       // b*L + l
    int br  = blockIdx.y;
    int b = row / Lseq, l = row % Lseq;

    if (threadIdx.x < XDBE)
        g_xdb[br][(long)row*XDBE + threadIdx.x] = 0.0f;
    if (br == 0)
        *(float2*)(&g_hidden[(long)row*D + threadIdx.x*2]) = make_float2(0.f, 0.f);

    const float* w  = br ? cwb : cw;
    const float* bb = br ? cbb : cb;
    int d0 = threadIdx.x * 4;   // blockDim = 192
    if (d0 >= DIN) return;

    float4 wv[4];
    #pragma unroll
    for (int j = 0; j < 4; j++) wv[j] = *(const float4*)(w + (d0 + j)*4);
    float4 acc = *(const float4*)(bb + d0);

    #pragma unroll
    for (int k = 0; k < 4; k++) {
        int li = l - 3 + k;
        if (li >= 0) {
            int lsrc = br ? (Lseq - 1 - li) : li;
            float4 x = *(const float4*)(&g_xz[((long)b*Lseq + lsrc)*(2*DIN) + d0]);
            acc.x = fmaf(x.x, ((const float*)&wv[0])[k], acc.x);
            acc.y = fmaf(x.y, ((const float*)&wv[1])[k], acc.y);
            acc.z = fmaf(x.z, ((const float*)&wv[2])[k], acc.z);
            acc.w = fmaf(x.w, ((const float*)&wv[3])[k], acc.w);
        }
    }
    float4 o;
    o.x = silu_f(acc.x); o.y = silu_f(acc.y);
    o.z = silu_f(acc.z); o.w = silu_f(acc.w);
    *(float4*)(&g_xc[br][((long)b*Lseq + l)*DIN + d0]) = o;
}

// ---------------- SSM scan: thread = (b, d, n-pair); 4-step software pipeline ----------------
__global__ void ssm_kernel(const float* __restrict__ Alog0, const float* __restrict__ Alog1,
                           const float* __restrict__ Dp0,   const float* __restrict__ Dp1)
{
    int br = blockIdx.z, b = blockIdx.y;
    int tid = threadIdx.x;            // 128 = 16 d x 8 n-pairs
    int n2 = tid & 7;                 // handles n = 2*n2, 2*n2+1
    int d = blockIdx.x * 16 + (tid >> 3);

    const float* Alog = br ? Alog1 : Alog0;
    float2 Ac = *(const float2*)(Alog + d*Nst + 2*n2);
    float A0 = -__expf(Ac.x), A1 = -__expf(Ac.y);
    float Dv = (br ? Dp1 : Dp0)[d];

    const float* dt_p  = g_dt[br]  + (long)b*Lseq*DIN + d;
    const float* xc_p  = g_xc[br]  + (long)b*Lseq*DIN + d;
    const float* xdb_p = g_xdb[br] + (long)b*Lseq*XDBE;
    float*       y_p   = g_y[br]   + (long)b*Lseq*DIN + d;
    const float* z_p   = g_xz + (long)b*Lseq*(2*DIN) + DIN + d;

    float h0 = 0.f, h1 = 0.f;
    float dtv[4], xcv[4];
    float2 Bv[4], Cv[4];
    #pragma unroll
    for (int j = 0; j < 4; j++) {
        int l = (j < Lseq) ? j : Lseq - 1;
        dtv[j] = dt_p[(long)l*DIN];
        xcv[j] = xc_p[(long)l*DIN];
        Bv[j] = *(const float2*)(xdb_p + l*XDBE + DTR + 2*n2);
        Cv[j] = *(const float2*)(xdb_p + l*XDBE + DTR + Nst + 2*n2);
    }

    for (int l0 = 0; l0 < Lseq; l0 += 4) {
        float dtn[4], xcn[4];
        float2 Bn[4], Cn[4];
        #pragma unroll
        for (int j = 0; j < 4; j++) {
            int ln = l0 + 4 + j;
            if (ln > Lseq - 1) ln = Lseq - 1;
            dtn[j] = dt_p[(long)ln*DIN];
            xcn[j] = xc_p[(long)ln*DIN];
            Bn[j] = *(const float2*)(xdb_p + ln*XDBE + DTR + 2*n2);
            Cn[j] = *(const float2*)(xdb_p + ln*XDBE + DTR + Nst + 2*n2);
        }
        #pragma unroll
        for (int j = 0; j < 4; j++) {
            int l = l0 + j;
            if (l < Lseq) {
                float e0 = __expf(dtv[j] * A0);
                float e1 = __expf(dtv[j] * A1);
                float dx = dtv[j] * xcv[j];
                h0 = fmaf(e0, h0, dx * Bv[j].x);
                h1 = fmaf(e1, h1, dx * Bv[j].y);
                float p = h0 * Cv[j].x + h1 * Cv[j].y;
                p += __shfl_xor_sync(~0u, p, 4);
                p += __shfl_xor_sync(~0u, p, 2);
                p += __shfl_xor_sync(~0u, p, 1);
                if (n2 == 0) {
                    int lz = br ? (Lseq - 1 - l) : l;
                    float zv = z_p[(long)lz*(2*DIN)];
                    y_p[(long)l*DIN] = (p + xcv[j] * Dv) * silu_f(zv);
                }
            }
        }
        #pragma unroll
        for (int j = 0; j < 4; j++) {
            dtv[j] = dtn[j]; xcv[j] = xcn[j]; Bv[j] = Bn[j]; Cv[j] = Cn[j];
        }
    }
}

// ---------------- final: residual + LN at POS + cmd MLP ----------------
__global__ void final_kernel(const float* __restrict__ state_vec, const float* __restrict__ action,
                             const float* __restrict__ lnf_w, const float* __restrict__ lnf_b,
                             const float* __restrict__ cw1, const float* __restrict__ cb1,
                             const float* __restrict__ cw2, const float* __restrict__ cb2,
                             float* __restrict__ out)
{
    int b = blockIdx.x, t = threadIdx.x;    // 384 threads
    long off = ((long)b*Lseq + POS)*D + t;
    float v = g_hidden[off] + g_resid[off];

    float s = v, q = v*v;
    #pragma unroll
    for (int o = 16; o > 0; o >>= 1) {
        s += __shfl_xor_sync(~0u, s, o);
        q += __shfl_xor_sync(~0u, q, o);
    }
    __shared__ float rs[12], rq[12];
    __shared__ float s_mean, s_rstd;
    __shared__ float s_cmd[20];
    __shared__ float s_r1[D];
    int w = t >> 5, ln = t & 31;
    if (ln == 0) { rs[w] = s; rq[w] = q; }
    __syncthreads();
    if (t == 0) {
        float ss = 0.f, qq = 0.f;
        #pragma unroll
        for (int i = 0; i < 12; i++) { ss += rs[i]; qq += rq[i]; }
        float m = ss / D;
        s_mean = m;
        s_rstd = rsqrtf(qq / D - m*m + 1e-5f);
    }
    if (t < 16)      s_cmd[t] = state_vec[b*16 + t];
    else if (t < 20) s_cmd[t] = action[b*4 + t - 16];
    __syncthreads();

    float h = (v - s_mean) * s_rstd * lnf_w[t] + lnf_b[t];

    float r1 = cb1[t];
    #pragma unroll
    for (int j = 0; j < 20; j++) r1 = fmaf(s_cmd[j], cw1[t*20 + j], r1);
    s_r1[t] = fmaxf(r1, 0.0f);
    __syncthreads();

    float o2 = cb2[t];
    for (int e = 0; e < D; e++) o2 = fmaf(s_r1[e], cw2[t*D + e], o2);
    out[b*D + t] = h + o2;
}

// ---------------- host launcher ----------------
extern "C" void kernel_launch(void* const* d_in, const int* in_sizes, int n_in,
                              void* d_out, int out_size)
{
    const float* depth_seq = (const float*)d_in[0];
    const float* state_vec = (const float*)d_in[1];
    const float* action    = (const float*)d_in[2];
    const float* patch_w   = (const float*)d_in[3];
    const float* patch_b   = (const float*)d_in[4];
    const float* cls_token = (const float*)d_in[5];
    const float* pos_embed = (const float*)d_in[6];
    const float* ln_w      = (const float*)d_in[7];
    const float* ln_b      = (const float*)d_in[8];
    const float* in_proj_w = (const float*)d_in[9];
    const float* conv_w    = (const float*)d_in[10];
    const float* conv_b    = (const float*)d_in[11];
    const float* conv_wb   = (const float*)d_in[12];
    const float* conv_bb   = (const float*)d_in[13];
    const float* xproj_w   = (const float*)d_in[14];
    const float* xproj_wb  = (const float*)d_in[15];
    const float* dtproj_w  = (const float*)d_in[16];
    const float* dtproj_b  = (const float*)d_in[17];
    const float* dtproj_wb = (const float*)d_in[18];
    const float* dtproj_bb = (const float*)d_in[19];
    const float* A_log     = (const float*)d_in[20];
    const float* A_logb    = (const float*)d_in[21];
    const float* Dp        = (const float*)d_in[22];
    const float* Dpb       = (const float*)d_in[23];
    const float* out_w     = (const float*)d_in[24];
    const float* lnf_w     = (const float*)d_in[25];
    const float* lnf_b     = (const float*)d_in[26];
    const float* cw1       = (const float*)d_in[27];
    const float* cb1       = (const float*)d_in[28];
    const float* cw2       = (const float*)d_in[29];
    const float* cb2       = (const float*)d_in[30];
    float* out = (float*)d_out;

    float *p_xr, *p_tok, *p_hn, *p_xz, *p_xc, *p_xdb, *p_y0, *p_y1, *p_hidden, *p_dt;
    cudaGetSymbolAddress((void**)&p_xr,     g_xr);
    cudaGetSymbolAddress((void**)&p_tok,    g_tok);
    cudaGetSymbolAddress((void**)&p_hn,     g_hn);
    cudaGetSymbolAddress((void**)&p_xz,     g_xz);
    cudaGetSymbolAddress((void**)&p_xc,     g_xc);
    cudaGetSymbolAddress((void**)&p_xdb,    g_xdb);
    cudaGetSymbolAddress((void**)&p_hidden, g_hidden);
    cudaGetSymbolAddress((void**)&p_dt,     g_dt);
    {
        float* base;
        cudaGetSymbolAddress((void**)&base, g_y);
        p_y0 = base;
        p_y1 = base + (long)Bc*Lseq*DIN;
    }

    // 1) patchify (+ zero g_tok) + patch-embed GEMM split-K x4 (atomic)
    patchify_kernel<<<(Bc*NTOK*256 + 255)/256, 256>>>(depth_seq);
    {
        dim3 g(D/64, (Bc*NTOK)/128, 4);
        mma_gemm_kernel<<<g, 256>>>(p_xr, nullptr, patch_w, nullptr, nullptr, nullptr,
                                    p_tok, Bc*NTOK, D, 256, 256, D, 0, 0, 0, 4);
    }

    // 2) layers
    for (int i = 0; i < DEPTH; i++) {
        resln_kernel<<<(MSEQ + 3)/4, 128>>>(ln_w + i*D, ln_b + i*D, cls_token, pos_embed, i == 0);

        {   // in_proj: (1028,384) @ (1536,384)^T -> g_xz
            dim3 g((2*DIN)/64, (MSEQ + 127)/128, 1);
            mma_gemm_kernel<<<g, 256>>>(p_hn, nullptr, in_proj_w + (long)i*2*DIN*D, nullptr,
                                        nullptr, nullptr, p_xz,
                                        MSEQ, 2*DIN, D, D, 2*DIN, 0, 0, 0, 1);
        }

        {   // conv + zero xdb/hidden rows for split-K accumulation
            dim3 g(MSEQ, 2);
            conv_kernel<<<g, 192>>>(conv_w + i*DIN*4, conv_b + i*DIN,
                                    conv_wb + i*DIN*4, conv_bb + i*DIN);
        }

        {   // xproj both branches, split-K x8 (atomic): (1028,768)@(56,768)^T -> g_xdb
            dim3 g(1, (MSEQ + 127)/128, 2*8);
            mma_gemm_kernel<<<g, 256>>>(p_xc, nullptr,
                                        xproj_w + (long)i*XDBE*DIN, xproj_wb + (long)i*XDBE*DIN,
                                        nullptr, nullptr, p_xdb,
                                        MSEQ, XDBE, DIN, DIN, XDBE,
                                        (long)Bc*Lseq*DIN, (long)Bc*Lseq*XDBE, 0, 8);
        }

        {   // dtproj both branches, softplus: (1028,24 of 56) @ (768,24)^T -> g_dt
            dim3 g(DIN/64, (MSEQ + 127)/128, 2);
            mma_gemm_kernel<<<g, 256>>>(p_xdb, nullptr,
                                        dtproj_w + (long)i*DIN*DTR, dtproj_wb + (long)i*DIN*DTR,
                                        dtproj_b + i*DIN, dtproj_bb + i*DIN, p_dt,
                                        MSEQ, DIN, DTR, XDBE, DIN,
                                        (long)Bc*Lseq*XDBE, (long)Bc*Lseq*DIN, 2, 1);
        }

        {   dim3 g(DIN/16, Bc, 2);
            ssm_kernel<<<g, 128>>>(A_log + (long)i*DIN*Nst, A_logb + (long)i*DIN*Nst,
                                   Dp + i*DIN, Dpb + i*DIN);
        }

        {   // out_proj, combine fused (A = y0[m] + y1[flip(m)]), split-K x4 (atomic)
            dim3 g(D/64, (MSEQ + 127)/128, 4);
            mma_gemm_kernel<<<g, 256>>>(p_y0, p_y1, out_w + (long)i*D*DIN, nullptr,
                                        nullptr, nullptr, p_hidden,
                                        MSEQ, D, DIN, DIN, D, 0, 0, 0, 4);
        }
    }

    // 3) final LN at POS + command MLP
    final_kernel<<<Bc, D>>>(state_vec, action, lnf_w, lnf_b, cw1, cb1, cw2, cb2, out);
}

// round 11
// speedup vs baseline: 1.0100x; 1.0100x over previous
#include <cuda_runtime.h>
#include <math.h>
#include <stdint.h>

// ---------------- problem constants ----------------
#define Bc    4
#define Tt    4
#define Hh    128
#define Wd    128
#define D     384
#define DEPTH 4
#define DIN   768
#define Nst   16
#define DTR   24
#define NTOK  256
#define Lseq  257
#define POS   128
#define XDBE  56          // DTR + 2N
#define GWp   8           // W/P
#define MSEQ  (Bc*Lseq)   // 1028

// ---------------- scratch (device globals; no allocation allowed) ----------------
__device__ float g_xr[Bc*NTOK*256];
__device__ float g_tok[Bc*NTOK*D];
__device__ float g_resid[Bc*Lseq*D];
__device__ float g_hidden[Bc*Lseq*D];
__device__ float g_hn[Bc*Lseq*D];
__device__ float g_xz[Bc*Lseq*2*DIN];
__device__ float g_xc[2][Bc*Lseq*DIN];
__device__ float g_xdb[2][Bc*Lseq*XDBE];
__device__ float g_dt[2][Bc*Lseq*DIN];
__device__ float g_y[2][Bc*Lseq*DIN];

__device__ __forceinline__ float silu_f(float v) {
    return v / (1.0f + __expf(-v));
}

__device__ __forceinline__ uint32_t f2tf32(float v) {
    uint32_t o;
    asm("cvt.rna.tf32.f32 %0, %1;" : "=r"(o) : "f"(v));
    return o;
}

__device__ __forceinline__ void mma_tf32(float* c, const uint32_t* a, const uint32_t* b) {
    asm volatile(
        "mma.sync.aligned.m16n8k8.row.col.f32.tf32.tf32.f32 "
        "{%0,%1,%2,%3}, {%4,%5,%6,%7}, {%8,%9}, {%0,%1,%2,%3};"
        : "+f"(c[0]), "+f"(c[1]), "+f"(c[2]), "+f"(c[3])
        : "r"(a[0]), "r"(a[1]), "r"(a[2]), "r"(a[3]),
          "r"(b[0]), "r"(b[1]));
}

// ---------------- patchify: depth_seq -> xr; also zero g_tok (split-K target) ----------------
__global__ void patchify_kernel(const float* __restrict__ depth) {
    int idx = blockIdx.x * blockDim.x + threadIdx.x;
    int nthr = gridDim.x * blockDim.x;
    for (int i = idx; i < Bc*NTOK*D; i += nthr) g_tok[i] = 0.0f;
    if (idx >= Bc*NTOK*256) return;
    int j   = idx & 255;
    int tok = (idx >> 8) % NTOK;
    int b   = idx / (256*NTOK);
    int p2 = j & 15, p1 = j >> 4;
    int gw = tok % GWp, gh = tok / GWp;
    int y = gh*16 + p1, x = gw*16 + p2;
    g_xr[idx] = depth[((long)b*(Tt*Hh) + y)*Wd + x];
}

// ============ tensor-core tf32 GEMM: C (+)= act((A[m] + A2flip[flip(m)]) @ W^T + bias) ============
// 64x64 block tile, BK=16, 128 threads = 4 warps (2x2), warp tile 32x32, double-buffered.
// Permuted smem layout within each 8-k chunk: pos = (k%4)*2 + k/4  => a lane's (k, k+4)
// pair is one float2.
// ksplit > 1: grid.z = Zbr*ksplit, each slice covers nk/ksplit k-tiles, epilogue atomicAdd
// (no bias/act on that path).
#define GSTR 18     // 16 + 2 pad (floats)

__global__ __launch_bounds__(128) void mma_gemm_kernel(
    const float* __restrict__ A, const float* __restrict__ A2flip,
    const float* __restrict__ W0, const float* __restrict__ W1,
    const float* __restrict__ bias0, const float* __restrict__ bias1,
    float* __restrict__ C,
    int M, int N, int K, int lda, int ldc,
    long strideA, long strideC, int act, int ksplit)
{
    __shared__ float As[2][64][GSTR];
    __shared__ float Ws[2][64][GSTR];

    int z = blockIdx.z;
    int br = z / ksplit;
    int ks = z - br * ksplit;

    const float* Ap = A + (long)br * strideA;
    const float* Wp = br ? W1 : W0;
    const float* bp = br ? bias1 : bias0;
    float* Cp = C + (long)br * strideC;

    int tid  = threadIdx.x;
    int warp = tid >> 5, lane = tid & 31;
    int wm = warp >> 1, wn = warp & 1;
    int qr = lane >> 2, qc = lane & 3;
    int m0 = blockIdx.y * 64, n0 = blockIdx.x * 64;

    // staging: thread stages one A row-half and one W row-half (8 floats each)
    int srow = tid >> 1;          // 0..63
    int sc8  = (tid & 1) * 8;     // 0 or 8

    int am = m0 + srow;
    bool amok = (am < M);
    long aoff = (long)am * lda;
    long a2off = 0;
    if (A2flip) {
        int bb = am / Lseq, ll = am % Lseq;
        a2off = ((long)bb * Lseq + (Lseq - 1 - ll)) * lda;
    }
    int wrow = n0 + srow;
    bool wok = (wrow < N);
    long woff = (long)wrow * K;

    float acc[2][4][4];
    #pragma unroll
    for (int i = 0; i < 2; i++)
        #pragma unroll
        for (int j = 0; j < 4; j++)
            #pragma unroll
            for (int q = 0; q < 4; q++) acc[i][j][q] = 0.0f;

    int nk_total = (K + 15) / 16;
    int nk_s = nk_total / ksplit;
    int kt0 = ks * nk_s, kt1 = kt0 + nk_s;

    const float4 zero4 = make_float4(0.f, 0.f, 0.f, 0.f);
    float4 ra0, ra1, rw0, rw1;

    // hoisted fragment base pointers (per buffer)
    const float* paB[2] = { &As[0][wm*32 + qr][qc*2], &As[1][wm*32 + qr][qc*2] };
    const float* pwB[2] = { &Ws[0][wn*32 + qr][qc*2], &Ws[1][wn*32 + qr][qc*2] };

    // ---- prologue: load tile kt0 ----
    {
        int k = kt0 * 16 + sc8;
        bool k0ok = (k < K), k1ok = (k + 4 < K);
        ra0 = (amok && k0ok) ? *(const float4*)(Ap + aoff + k)     : zero4;
        ra1 = (amok && k1ok) ? *(const float4*)(Ap + aoff + k + 4) : zero4;
        if (A2flip && amok) {
            if (k0ok) { float4 t = *(const float4*)(A2flip + a2off + k);
                ra0.x += t.x; ra0.y += t.y; ra0.z += t.z; ra0.w += t.w; }
            if (k1ok) { float4 t = *(const float4*)(A2flip + a2off + k + 4);
                ra1.x += t.x; ra1.y += t.y; ra1.z += t.z; ra1.w += t.w; }
        }
        rw0 = (wok && k0ok) ? *(const float4*)(Wp + woff + k)     : zero4;
        rw1 = (wok && k1ok) ? *(const float4*)(Wp + woff + k + 4) : zero4;
    }
    {
        // permuted store: ra0 (k%4=0..3) -> pos 0,2,4,6 ; ra1 (k+4) -> pos 1,3,5,7
        float* pa = &As[0][srow][sc8];
        pa[0] = __uint_as_float(f2tf32(ra0.x)); pa[2] = __uint_as_float(f2tf32(ra0.y));
        pa[4] = __uint_as_float(f2tf32(ra0.z)); pa[6] = __uint_as_float(f2tf32(ra0.w));
        pa[1] = __uint_as_float(f2tf32(ra1.x)); pa[3] = __uint_as_float(f2tf32(ra1.y));
        pa[5] = __uint_as_float(f2tf32(ra1.z)); pa[7] = __uint_as_float(f2tf32(ra1.w));
        float* pw = &Ws[0][srow][sc8];
        pw[0] = __uint_as_float(f2tf32(rw0.x)); pw[2] = __uint_as_float(f2tf32(rw0.y));
        pw[4] = __uint_as_float(f2tf32(rw0.z)); pw[6] = __uint_as_float(f2tf32(rw0.w));
        pw[1] = __uint_as_float(f2tf32(rw1.x)); pw[3] = __uint_as_float(f2tf32(rw1.y));
        pw[5] = __uint_as_float(f2tf32(rw1.z)); pw[7] = __uint_as_float(f2tf32(rw1.w));
    }
    __syncthreads();

    for (int kt = kt0; kt < kt1; kt++) {
        int cur = (kt - kt0) & 1;
        if (kt + 1 < kt1) {
            int k = (kt + 1) * 16 + sc8;
            bool k0ok = (k < K), k1ok = (k + 4 < K);
            ra0 = (amok && k0ok) ? *(const float4*)(Ap + aoff + k)     : zero4;
            ra1 = (amok && k1ok) ? *(const float4*)(Ap + aoff + k + 4) : zero4;
            if (A2flip && amok) {
                if (k0ok) { float4 t = *(const float4*)(A2flip + a2off + k);
                    ra0.x += t.x; ra0.y += t.y; ra0.z += t.z; ra0.w += t.w; }
                if (k1ok) { float4 t = *(const float4*)(A2flip + a2off + k + 4);
                    ra1.x += t.x; ra1.y += t.y; ra1.z += t.z; ra1.w += t.w; }
            }
            rw0 = (wok && k0ok) ? *(const float4*)(Wp + woff + k)     : zero4;
            rw1 = (wok && k1ok) ? *(const float4*)(Wp + woff + k + 4) : zero4;
        }
        // ---- compute tile cur: 2 chunks of 8 k ----
        #pragma unroll
        for (int kk = 0; kk < 2; kk++) {
            int co = kk * 8;
            uint32_t afr[2][4];
            #pragma unroll
            for (int fm = 0; fm < 2; fm++) {
                const float* pa = paB[cur] + fm*16*GSTR + co;
                float2 lo = *(const float2*)pa;
                float2 hi = *(const float2*)(pa + 8*GSTR);
                afr[fm][0] = __float_as_uint(lo.x);
                afr[fm][1] = __float_as_uint(hi.x);
                afr[fm][2] = __float_as_uint(lo.y);
                afr[fm][3] = __float_as_uint(hi.y);
            }
            uint32_t bfr[4][2];
            #pragma unroll
            for (int fn = 0; fn < 4; fn++) {
                float2 bb = *(const float2*)(pwB[cur] + fn*8*GSTR + co);
                bfr[fn][0] = __float_as_uint(bb.x);
                bfr[fn][1] = __float_as_uint(bb.y);
            }
            #pragma unroll
            for (int fm = 0; fm < 2; fm++)
                #pragma unroll
                for (int fn = 0; fn < 4; fn++)
                    mma_tf32(acc[fm][fn], afr[fm], bfr[fn]);
        }
        if (kt + 1 < kt1) {
            int nxt = (kt + 1 - kt0) & 1;
            float* pa = &As[nxt][srow][sc8];
            pa[0] = __uint_as_float(f2tf32(ra0.x)); pa[2] = __uint_as_float(f2tf32(ra0.y));
            pa[4] = __uint_as_float(f2tf32(ra0.z)); pa[6] = __uint_as_float(f2tf32(ra0.w));
            pa[1] = __uint_as_float(f2tf32(ra1.x)); pa[3] = __uint_as_float(f2tf32(ra1.y));
            pa[5] = __uint_as_float(f2tf32(ra1.z)); pa[7] = __uint_as_float(f2tf32(ra1.w));
            float* pw = &Ws[nxt][srow][sc8];
            pw[0] = __uint_as_float(f2tf32(rw0.x)); pw[2] = __uint_as_float(f2tf32(rw0.y));
            pw[4] = __uint_as_float(f2tf32(rw0.z)); pw[6] = __uint_as_float(f2tf32(rw0.w));
            pw[1] = __uint_as_float(f2tf32(rw1.x)); pw[3] = __uint_as_float(f2tf32(rw1.y));
            pw[5] = __uint_as_float(f2tf32(rw1.z)); pw[7] = __uint_as_float(f2tf32(rw1.w));
            __syncthreads();
        }
    }

    // ---- epilogue ----
    bool do_atomic = (ksplit > 1);
    #pragma unroll
    for (int fm = 0; fm < 2; fm++) {
        #pragma unroll
        for (int fn = 0; fn < 4; fn++) {
            #pragma unroll
            for (int half = 0; half < 2; half++) {
                int m = m0 + wm*32 + fm*16 + qr + half*8;
                int ncol = n0 + wn*32 + fn*8 + qc*2;
                if (m >= M || ncol >= N) continue;
                float v0 = acc[fm][fn][half*2];
                float v1 = acc[fm][fn][half*2 + 1];
                if (do_atomic) {
                    atomicAdd(Cp + (long)m*ldc + ncol,     v0);
                    atomicAdd(Cp + (long)m*ldc + ncol + 1, v1);
                } else {
                    if (bp) { v0 += bp[ncol]; v1 += bp[ncol + 1]; }
                    if (act == 2) {
                        v0 = (v0 > 15.0f) ? v0 : log1pf(__expf(v0));
                        v1 = (v1 > 15.0f) ? v1 : log1pf(__expf(v1));
                    }
                    *(float2*)(Cp + (long)m*ldc + ncol) = make_float2(v0, v1);
                }
            }
        }
    }
}

// ---------------- residual accumulate + layernorm: warp per row, float4 ----------------
// first: assemble (tok/cls + pos_embed) fused in. Also zeroes g_xz row (in_proj split-K target).
__global__ void resln_kernel(const float* __restrict__ lw, const float* __restrict__ lb,
                             const float* __restrict__ cls, const float* __restrict__ pos,
                             int first) {
    int row = blockIdx.x * 4 + (threadIdx.x >> 5);
    if (row >= MSEQ) return;
    int lane = threadIdx.x & 31;
    long base = (long)row * D;

    // zero this row of g_xz (accumulated atomically by split-K in_proj)
    {
        float4 z4 = make_float4(0.f, 0.f, 0.f, 0.f);
        float* zr = g_xz + (long)row * (2*DIN);
        #pragma unroll
        for (int j = 0; j < 12; j++)
            *(float4*)(zr + (lane + j*32)*4) = z4;
    }

    float4 v[3];
    float s = 0.f, q = 0.f;
    if (first) {
        int b = row / Lseq, l = row % Lseq;
        const float* src;
        if (l < POS)       src = g_tok + ((long)b*NTOK + l)*D;
        else if (l == POS) src = cls;
        else               src = g_tok + ((long)b*NTOK + l - 1)*D;
        #pragma unroll
        for (int j = 0; j < 3; j++) {
            int d0 = (lane + j*32) * 4;
            float4 t = *(const float4*)(src + d0);
            float4 pe = *(const float4*)(pos + (long)l*D + d0);
            t.x += pe.x; t.y += pe.y; t.z += pe.z; t.w += pe.w;
            v[j] = t;
            s += t.x + t.y + t.z + t.w;
            q += t.x*t.x + t.y*t.y + t.z*t.z + t.w*t.w;
        }
    } else {
        #pragma unroll
        for (int j = 0; j < 3; j++) {
            int d0 = (lane + j*32) * 4;
            float4 t = *(const float4*)(&g_hidden[base + d0]);
            float4 r = *(const float4*)(&g_resid[base + d0]);
            t.x += r.x; t.y += r.y; t.z += r.z; t.w += r.w;
            v[j] = t;
            s += t.x + t.y + t.z + t.w;
            q += t.x*t.x + t.y*t.y + t.z*t.z + t.w*t.w;
        }
    }
    #pragma unroll
    for (int o = 16; o > 0; o >>= 1) {
        s += __shfl_xor_sync(~0u, s, o);
        q += __shfl_xor_sync(~0u, q, o);
    }
    float mean = s / D;
    float rstd = rsqrtf(q / D - mean*mean + 1e-5f);
    #pragma unroll
    for (int j = 0; j < 3; j++) {
        int d0 = (lane + j*32) * 4;
        *(float4*)(&g_resid[base + d0]) = v[j];
        float4 wv = *(const float4*)(lw + d0);
        float4 bv = *(const float4*)(lb + d0);
        float4 o;
        o.x = (v[j].x - mean)*rstd*wv.x + bv.x;
        o.y = (v[j].y - mean)*rstd*wv.y + bv.y;
        o.z = (v[j].z - mean)*rstd*wv.z + bv.z;
        o.w = (v[j].w - mean)*rstd*wv.w + bv.w;
        *(float4*)(&g_hn[base + d0]) = o;
    }
}

// ---------------- causal conv (K=4) + silu, both branches (float4) ----------------
// Also zeroes the split-K accumulation targets: g_xdb row (per br) and g_hidden row (br==0).
__global__ void conv_kernel(const float* __restrict__ cw,  const float* __restrict__ cb,
                            const float* __restrict__ cwb, const float* __restrict__ cbb)
{
    int row = blockIdx.x;       // b*L + l
    int br  = blockIdx.y;
    int b = row / Lseq, l = row % Lseq;

    if (threadIdx.x < XDBE)
        g_xdb[br][(long)row*XDBE + threadIdx.x] = 0.0f;
    if (br == 0)
        *(float2*)(&g_hidden[(long)row*D + threadIdx.x*2]) = make_float2(0.f, 0.f);

    const float* w  = br ? cwb : cw;
    const float* bb = br ? cbb : cb;
    int d0 = threadIdx.x * 4;   // blockDim = 192
    if (d0 >= DIN) return;

    float4 wv[4];
    #pragma unroll
    for (int j = 0; j < 4; j++) wv[j] = *(const float4*)(w + (d0 + j)*4);
    float4 acc = *(const float4*)(bb + d0);

    #pragma unroll
    for (int k = 0; k < 4; k++) {
        int li = l - 3 + k;
        if (li >= 0) {
            int lsrc = br ? (Lseq - 1 - li) : li;
            float4 x = *(const float4*)(&g_xz[((long)b*Lseq + lsrc)*(2*DIN) + d0]);
            acc.x = fmaf(x.x, ((const float*)&wv[0])[k], acc.x);
            acc.y = fmaf(x.y, ((const float*)&wv[1])[k], acc.y);
            acc.z = fmaf(x.z, ((const float*)&wv[2])[k], acc.z);
            acc.w = fmaf(x.w, ((const float*)&wv[3])[k], acc.w);
        }
    }
    float4 o;
    o.x = silu_f(acc.x); o.y = silu_f(acc.y);
    o.z = silu_f(acc.z); o.w = silu_f(acc.w);
    *(float4*)(&g_xc[br][((long)b*Lseq + l)*DIN + d0]) = o;
}

// ---------------- SSM scan: thread = (b, d, n-pair); 4-step software pipeline ----------------
__global__ void ssm_kernel(const float* __restrict__ Alog0, const float* __restrict__ Alog1,
                           const float* __restrict__ Dp0,   const float* __restrict__ Dp1)
{
    int br = blockIdx.z, b = blockIdx.y;
    int tid = threadIdx.x;            // 128 = 16 d x 8 n-pairs
    int n2 = tid & 7;                 // handles n = 2*n2, 2*n2+1
    int d = blockIdx.x * 16 + (tid >> 3);

    const float* Alog = br ? Alog1 : Alog0;
    float2 Ac = *(const float2*)(Alog + d*Nst + 2*n2);
    float A0 = -__expf(Ac.x), A1 = -__expf(Ac.y);
    float Dv = (br ? Dp1 : Dp0)[d];

    const float* dt_p  = g_dt[br]  + (long)b*Lseq*DIN + d;
    const float* xc_p  = g_xc[br]  + (long)b*Lseq*DIN + d;
    const float* xdb_p = g_xdb[br] + (long)b*Lseq*XDBE;
    float*       y_p   = g_y[br]   + (long)b*Lseq*DIN + d;
    const float* z_p   = g_xz + (long)b*Lseq*(2*DIN) + DIN + d;

    float h0 = 0.f, h1 = 0.f;
    float dtv[4], xcv[4];
    float2 Bv[4], Cv[4];
    #pragma unroll
    for (int j = 0; j < 4; j++) {
        int l = (j < Lseq) ? j : Lseq - 1;
        dtv[j] = dt_p[(long)l*DIN];
        xcv[j] = xc_p[(long)l*DIN];
        Bv[j] = *(const float2*)(xdb_p + l*XDBE + DTR + 2*n2);
        Cv[j] = *(const float2*)(xdb_p + l*XDBE + DTR + Nst + 2*n2);
    }

    for (int l0 = 0; l0 < Lseq; l0 += 4) {
        float dtn[4], xcn[4];
        float2 Bn[4], Cn[4];
        #pragma unroll
        for (int j = 0; j < 4; j++) {
            int ln = l0 + 4 + j;
            if (ln > Lseq - 1) ln = Lseq - 1;
            dtn[j] = dt_p[(long)ln*DIN];
            xcn[j] = xc_p[(long)ln*DIN];
            Bn[j] = *(const float2*)(xdb_p + ln*XDBE + DTR + 2*n2);
            Cn[j] = *(const float2*)(xdb_p + ln*XDBE + DTR + Nst + 2*n2);
        }
        #pragma unroll
        for (int j = 0; j < 4; j++) {
            int l = l0 + j;
            if (l < Lseq) {
                float e0 = __expf(dtv[j] * A0);
                float e1 = __expf(dtv[j] * A1);
                float dx = dtv[j] * xcv[j];
                h0 = fmaf(e0, h0, dx * Bv[j].x);
                h1 = fmaf(e1, h1, dx * Bv[j].y);
                float p = h0 * Cv[j].x + h1 * Cv[j].y;
                p += __shfl_xor_sync(~0u, p, 4);
                p += __shfl_xor_sync(~0u, p, 2);
                p += __shfl_xor_sync(~0u, p, 1);
                if (n2 == 0) {
                    int lz = br ? (Lseq - 1 - l) : l;
                    float zv = z_p[(long)lz*(2*DIN)];
                    y_p[(long)l*DIN] = (p + xcv[j] * Dv) * silu_f(zv);
                }
            }
        }
        #pragma unroll
        for (int j = 0; j < 4; j++) {
            dtv[j] = dtn[j]; xcv[j] = xcn[j]; Bv[j] = Bn[j]; Cv[j] = Cn[j];
        }
    }
}

// ---------------- final: residual + LN at POS + cmd MLP ----------------
__global__ void final_kernel(const float* __restrict__ state_vec, const float* __restrict__ action,
                             const float* __restrict__ lnf_w, const float* __restrict__ lnf_b,
                             const float* __restrict__ cw1, const float* __restrict__ cb1,
                             const float* __restrict__ cw2, const float* __restrict__ cb2,
                             float* __restrict__ out)
{
    int b = blockIdx.x, t = threadIdx.x;    // 384 threads
    long off = ((long)b*Lseq + POS)*D + t;
    float v = g_hidden[off] + g_resid[off];

    float s = v, q = v*v;
    #pragma unroll
    for (int o = 16; o > 0; o >>= 1) {
        s += __shfl_xor_sync(~0u, s, o);
        q += __shfl_xor_sync(~0u, q, o);
    }
    __shared__ float rs[12], rq[12];
    __shared__ float s_mean, s_rstd;
    __shared__ float s_cmd[20];
    __shared__ float s_r1[D];
    int w = t >> 5, ln = t & 31;
    if (ln == 0) { rs[w] = s; rq[w] = q; }
    __syncthreads();
    if (t == 0) {
        float ss = 0.f, qq = 0.f;
        #pragma unroll
        for (int i = 0; i < 12; i++) { ss += rs[i]; qq += rq[i]; }
        float m = ss / D;
        s_mean = m;
        s_rstd = rsqrtf(qq / D - m*m + 1e-5f);
    }
    if (t < 16)      s_cmd[t] = state_vec[b*16 + t];
    else if (t < 20) s_cmd[t] = action[b*4 + t - 16];
    __syncthreads();

    float h = (v - s_mean) * s_rstd * lnf_w[t] + lnf_b[t];

    float r1 = cb1[t];
    #pragma unroll
    for (int j = 0; j < 20; j++) r1 = fmaf(s_cmd[j], cw1[t*20 + j], r1);
    s_r1[t] = fmaxf(r1, 0.0f);
    __syncthreads();

    float o2 = cb2[t];
    for (int e = 0; e < D; e++) o2 = fmaf(s_r1[e], cw2[t*D + e], o2);
    out[b*D + t] = h + o2;
}

// ---------------- host launcher ----------------
extern "C" void kernel_launch(void* const* d_in, const int* in_sizes, int n_in,
                              void* d_out, int out_size)
{
    const float* depth_seq = (const float*)d_in[0];
    const float* state_vec = (const float*)d_in[1];
    const float* action    = (const float*)d_in[2];
    const float* patch_w   = (const float*)d_in[3];
    const float* patch_b   = (const float*)d_in[4];
    const float* cls_token = (const float*)d_in[5];
    const float* pos_embed = (const float*)d_in[6];
    const float* ln_w      = (const float*)d_in[7];
    const float* ln_b      = (const float*)d_in[8];
    const float* in_proj_w = (const float*)d_in[9];
    const float* conv_w    = (const float*)d_in[10];
    const float* conv_b    = (const float*)d_in[11];
    const float* conv_wb   = (const float*)d_in[12];
    const float* conv_bb   = (const float*)d_in[13];
    const float* xproj_w   = (const float*)d_in[14];
    const float* xproj_wb  = (const float*)d_in[15];
    const float* dtproj_w  = (const float*)d_in[16];
    const float* dtproj_b  = (const float*)d_in[17];
    const float* dtproj_wb = (const float*)d_in[18];
    const float* dtproj_bb = (const float*)d_in[19];
    const float* A_log     = (const float*)d_in[20];
    const float* A_logb    = (const float*)d_in[21];
    const float* Dp        = (const float*)d_in[22];
    const float* Dpb       = (const float*)d_in[23];
    const float* out_w     = (const float*)d_in[24];
    const float* lnf_w     = (const float*)d_in[25];
    const float* lnf_b     = (const float*)d_in[26];
    const float* cw1       = (const float*)d_in[27];
    const float* cb1       = (const float*)d_in[28];
    const float* cw2       = (const float*)d_in[29];
    const float* cb2       = (const float*)d_in[30];
    float* out = (float*)d_out;

    float *p_xr, *p_tok, *p_hn, *p_xz, *p_xc, *p_xdb, *p_y0, *p_y1, *p_hidden, *p_dt;
    cudaGetSymbolAddress((void**)&p_xr,     g_xr);
    cudaGetSymbolAddress((void**)&p_tok,    g_tok);
    cudaGetSymbolAddress((void**)&p_hn,     g_hn);
    cudaGetSymbolAddress((void**)&p_xz,     g_xz);
    cudaGetSymbolAddress((void**)&p_xc,     g_xc);
    cudaGetSymbolAddress((void**)&p_xdb,    g_xdb);
    cudaGetSymbolAddress((void**)&p_hidden, g_hidden);
    cudaGetSymbolAddress((void**)&p_dt,     g_dt);
    {
        float* base;
        cudaGetSymbolAddress((void**)&base, g_y);
        p_y0 = base;
        p_y1 = base + (long)Bc*Lseq*DIN;
    }

    // 1) patchify (+ zero g_tok) + patch-embed GEMM split-K x4 (atomic; patch_b == 0)
    patchify_kernel<<<(Bc*NTOK*256 + 255)/256, 256>>>(depth_seq);
    {
        dim3 g(D/64, (Bc*NTOK)/64, 4);
        mma_gemm_kernel<<<g, 128>>>(p_xr, nullptr, patch_w, nullptr, nullptr, nullptr,
                                    p_tok, Bc*NTOK, D, 256, 256, D, 0, 0, 0, 4);
    }

    // 2) layers
    for (int i = 0; i < DEPTH; i++) {
        resln_kernel<<<(MSEQ + 3)/4, 128>>>(ln_w + i*D, ln_b + i*D, cls_token, pos_embed, i == 0);

        {   // in_proj: (1028,384) @ (1536,384)^T -> g_xz, split-K x2 (atomic; no bias)
            dim3 g((2*DIN)/64, (MSEQ + 63)/64, 2);
            mma_gemm_kernel<<<g, 128>>>(p_hn, nullptr, in_proj_w + (long)i*2*DIN*D, nullptr,
                                        nullptr, nullptr, p_xz,
                                        MSEQ, 2*DIN, D, D, 2*DIN, 0, 0, 0, 2);
        }

        {   // conv + zero xdb/hidden rows for split-K accumulation
            dim3 g(MSEQ, 2);
            conv_kernel<<<g, 192>>>(conv_w + i*DIN*4, conv_b + i*DIN,
                                    conv_wb + i*DIN*4, conv_bb + i*DIN);
        }

        {   // xproj both branches, split-K x8 (atomic): (1028,768)@(56,768)^T -> g_xdb
            dim3 g(1, (MSEQ + 63)/64, 2*8);
            mma_gemm_kernel<<<g, 128>>>(p_xc, nullptr,
                                        xproj_w + (long)i*XDBE*DIN, xproj_wb + (long)i*XDBE*DIN,
                                        nullptr, nullptr, p_xdb,
                                        MSEQ, XDBE, DIN, DIN, XDBE,
                                        (long)Bc*Lseq*DIN, (long)Bc*Lseq*XDBE, 0, 8);
        }

        {   // dtproj both branches, softplus: (1028,24 of 56) @ (768,24)^T -> g_dt
            dim3 g(DIN/64, (MSEQ + 63)/64, 2);
            mma_gemm_kernel<<<g, 128>>>(p_xdb, nullptr,
                                        dtproj_w + (long)i*DIN*DTR, dtproj_wb + (long)i*DIN*DTR,
                                        dtproj_b + i*DIN, dtproj_bb + i*DIN, p_dt,
                                        MSEQ, DIN, DTR, XDBE, DIN,
                                        (long)Bc*Lseq*XDBE, (long)Bc*Lseq*DIN, 2, 1);
        }

        {   dim3 g(DIN/16, Bc, 2);
            ssm_kernel<<<g, 128>>>(A_log + (long)i*DIN*Nst, A_logb + (long)i*DIN*Nst,
                                   Dp + i*DIN, Dpb + i*DIN);
        }

        {   // out_proj, combine fused (A = y0[m] + y1[flip(m)]), split-K x4 (atomic)
            dim3 g(D/64, (MSEQ + 63)/64, 4);
            mma_gemm_kernel<<<g, 128>>>(p_y0, p_y1, out_w + (long)i*D*DIN, nullptr,
                                        nullptr, nullptr, p_hidden,
                                        MSEQ, D, DIN, DIN, D, 0, 0, 0, 4);
        }
    }

    // 3) final LN at POS + command MLP
    final_kernel<<<Bc, D>>>(state_vec, action, lnf_w, lnf_b, cw1, cb1, cw2, cb2, out);
}

// round 13
// speedup vs baseline: 1.3634x; 1.3500x over previous
#include <cuda_runtime.h>
#include <math.h>
#include <stdint.h>

// ---------------- problem constants ----------------
#define Bc    4
#define Tt    4
#define Hh    128
#define Wd    128
#define D     384
#define DEPTH 4
#define DIN   768
#define Nst   16
#define DTR   24
#define NTOK  256
#define Lseq  257
#define POS   128
#define XDBE  56          // DTR + 2N
#define GWp   8           // W/P
#define MSEQ  (Bc*Lseq)   // 1028
#define NCH   8           // scan chunks
#define CS    33          // chunk size (8*33 = 264 >= 257)

// ---------------- scratch (device globals; no allocation allowed) ----------------
__device__ float g_xr[Bc*NTOK*256];
__device__ float g_tok[Bc*NTOK*D];
__device__ float g_resid[Bc*Lseq*D];
__device__ float g_hidden[Bc*Lseq*D];
__device__ float g_hn[Bc*Lseq*D];
__device__ float g_xz[Bc*Lseq*2*DIN];
__device__ float g_xc[2][Bc*Lseq*DIN];
__device__ float g_xdb[2][Bc*Lseq*XDBE];
__device__ float g_dt[2][Bc*Lseq*DIN];
__device__ float g_y[2][Bc*Lseq*DIN];
__device__ float2 g_cs[2][Bc][NCH][DIN][Nst];   // per-chunk (hB, P)

__device__ __forceinline__ float silu_f(float v) {
    return v / (1.0f + __expf(-v));
}

__device__ __forceinline__ uint32_t f2tf32(float v) {
    uint32_t o;
    asm("cvt.rna.tf32.f32 %0, %1;" : "=r"(o) : "f"(v));
    return o;
}

__device__ __forceinline__ void mma_tf32(float* c, const uint32_t* a, const uint32_t* b) {
    asm volatile(
        "mma.sync.aligned.m16n8k8.row.col.f32.tf32.tf32.f32 "
        "{%0,%1,%2,%3}, {%4,%5,%6,%7}, {%8,%9}, {%0,%1,%2,%3};"
        : "+f"(c[0]), "+f"(c[1]), "+f"(c[2]), "+f"(c[3])
        : "r"(a[0]), "r"(a[1]), "r"(a[2]), "r"(a[3]),
          "r"(b[0]), "r"(b[1]));
}

// ---------------- patchify: depth_seq -> xr (B, NTOK, 256) ----------------
__global__ void patchify_kernel(const float* __restrict__ depth) {
    int idx = blockIdx.x * blockDim.x + threadIdx.x;
    if (idx >= Bc*NTOK*256) return;
    int j   = idx & 255;
    int tok = (idx >> 8) % NTOK;
    int b   = idx / (256*NTOK);
    int p2 = j & 15, p1 = j >> 4;
    int gw = tok % GWp, gh = tok / GWp;
    int y = gh*16 + p1, x = gw*16 + p2;
    g_xr[idx] = depth[((long)b*(Tt*Hh) + y)*Wd + x];
}

// ============ tensor-core tf32 GEMM: C (+)= act((A[m] + A2flip[flip(m)]) @ W^T + bias) ============
// 64x64 block tile, BK=16, 128 threads = 4 warps (2x2), warp tile 32x32, double-buffered.
// Permuted smem layout within each 8-k chunk: a lane's (k, k+4) pair is one float2.
// ksplit > 1: grid.z = Zbr*ksplit, each slice covers nk/ksplit k-tiles, epilogue atomicAdd.
#define GSTR 18     // 16 + 2 pad (floats)

__global__ __launch_bounds__(128) void mma_gemm_kernel(
    const float* __restrict__ A, const float* __restrict__ A2flip,
    const float* __restrict__ W0, const float* __restrict__ W1,
    const float* __restrict__ bias0, const float* __restrict__ bias1,
    float* __restrict__ C,
    int M, int N, int K, int lda, int ldc,
    long strideA, long strideC, int act, int ksplit)
{
    __shared__ float As[2][64][GSTR];
    __shared__ float Ws[2][64][GSTR];

    int z = blockIdx.z;
    int br = z / ksplit;
    int ks = z - br * ksplit;

    const float* Ap = A + (long)br * strideA;
    const float* Wp = br ? W1 : W0;
    const float* bp = br ? bias1 : bias0;
    float* Cp = C + (long)br * strideC;

    int tid  = threadIdx.x;
    int warp = tid >> 5, lane = tid & 31;
    int wm = warp >> 1, wn = warp & 1;
    int qr = lane >> 2, qc = lane & 3;
    int m0 = blockIdx.y * 64, n0 = blockIdx.x * 64;

    int srow = tid >> 1;          // 0..63
    int sc8  = (tid & 1) * 8;     // 0 or 8

    int am = m0 + srow;
    bool amok = (am < M);
    long aoff = (long)am * lda;
    long a2off = 0;
    if (A2flip) {
        int bb = am / Lseq, ll = am % Lseq;
        a2off = ((long)bb * Lseq + (Lseq - 1 - ll)) * lda;
    }
    int wrow = n0 + srow;
    bool wok = (wrow < N);
    long woff = (long)wrow * K;

    float acc[2][4][4];
    #pragma unroll
    for (int i = 0; i < 2; i++)
        #pragma unroll
        for (int j = 0; j < 4; j++)
            #pragma unroll
            for (int q = 0; q < 4; q++) acc[i][j][q] = 0.0f;

    int nk_total = (K + 15) / 16;
    int nk_s = nk_total / ksplit;
    int kt0 = ks * nk_s, kt1 = kt0 + nk_s;

    const float4 zero4 = make_float4(0.f, 0.f, 0.f, 0.f);
    float4 ra0, ra1, rw0, rw1;

    const float* paB[2] = { &As[0][wm*32 + qr][qc*2], &As[1][wm*32 + qr][qc*2] };
    const float* pwB[2] = { &Ws[0][wn*32 + qr][qc*2], &Ws[1][wn*32 + qr][qc*2] };

    // ---- prologue: load tile kt0 ----
    {
        int k = kt0 * 16 + sc8;
        bool k0ok = (k < K), k1ok = (k + 4 < K);
        ra0 = (amok && k0ok) ? *(const float4*)(Ap + aoff + k)     : zero4;
        ra1 = (amok && k1ok) ? *(const float4*)(Ap + aoff + k + 4) : zero4;
        if (A2flip && amok) {
            if (k0ok) { float4 t = *(const float4*)(A2flip + a2off + k);
                ra0.x += t.x; ra0.y += t.y; ra0.z += t.z; ra0.w += t.w; }
            if (k1ok) { float4 t = *(const float4*)(A2flip + a2off + k + 4);
                ra1.x += t.x; ra1.y += t.y; ra1.z += t.z; ra1.w += t.w; }
        }
        rw0 = (wok && k0ok) ? *(const float4*)(Wp + woff + k)     : zero4;
        rw1 = (wok && k1ok) ? *(const float4*)(Wp + woff + k + 4) : zero4;
    }
    {
        float* pa = &As[0][srow][sc8];
        pa[0] = __uint_as_float(f2tf32(ra0.x)); pa[2] = __uint_as_float(f2tf32(ra0.y));
        pa[4] = __uint_as_float(f2tf32(ra0.z)); pa[6] = __uint_as_float(f2tf32(ra0.w));
        pa[1] = __uint_as_float(f2tf32(ra1.x)); pa[3] = __uint_as_float(f2tf32(ra1.y));
        pa[5] = __uint_as_float(f2tf32(ra1.z)); pa[7] = __uint_as_float(f2tf32(ra1.w));
        float* pw = &Ws[0][srow][sc8];
        pw[0] = __uint_as_float(f2tf32(rw0.x)); pw[2] = __uint_as_float(f2tf32(rw0.y));
        pw[4] = __uint_as_float(f2tf32(rw0.z)); pw[6] = __uint_as_float(f2tf32(rw0.w));
        pw[1] = __uint_as_float(f2tf32(rw1.x)); pw[3] = __uint_as_float(f2tf32(rw1.y));
        pw[5] = __uint_as_float(f2tf32(rw1.z)); pw[7] = __uint_as_float(f2tf32(rw1.w));
    }
    __syncthreads();

    for (int kt = kt0; kt < kt1; kt++) {
        int cur = (kt - kt0) & 1;
        if (kt + 1 < kt1) {
            int k = (kt + 1) * 16 + sc8;
            bool k0ok = (k < K), k1ok = (k + 4 < K);
            ra0 = (amok && k0ok) ? *(const float4*)(Ap + aoff + k)     : zero4;
            ra1 = (amok && k1ok) ? *(const float4*)(Ap + aoff + k + 4) : zero4;
            if (A2flip && amok) {
                if (k0ok) { float4 t = *(const float4*)(A2flip + a2off + k);
                    ra0.x += t.x; ra0.y += t.y; ra0.z += t.z; ra0.w += t.w; }
                if (k1ok) { float4 t = *(const float4*)(A2flip + a2off + k + 4);
                    ra1.x += t.x; ra1.y += t.y; ra1.z += t.z; ra1.w += t.w; }
            }
            rw0 = (wok && k0ok) ? *(const float4*)(Wp + woff + k)     : zero4;
            rw1 = (wok && k1ok) ? *(const float4*)(Wp + woff + k + 4) : zero4;
        }
        #pragma unroll
        for (int kk = 0; kk < 2; kk++) {
            int co = kk * 8;
            uint32_t afr[2][4];
            #pragma unroll
            for (int fm = 0; fm < 2; fm++) {
                const float* pa = paB[cur] + fm*16*GSTR + co;
                float2 lo = *(const float2*)pa;
                float2 hi = *(const float2*)(pa + 8*GSTR);
                afr[fm][0] = __float_as_uint(lo.x);
                afr[fm][1] = __float_as_uint(hi.x);
                afr[fm][2] = __float_as_uint(lo.y);
                afr[fm][3] = __float_as_uint(hi.y);
            }
            uint32_t bfr[4][2];
            #pragma unroll
            for (int fn = 0; fn < 4; fn++) {
                float2 bb = *(const float2*)(pwB[cur] + fn*8*GSTR + co);
                bfr[fn][0] = __float_as_uint(bb.x);
                bfr[fn][1] = __float_as_uint(bb.y);
            }
            #pragma unroll
            for (int fm = 0; fm < 2; fm++)
                #pragma unroll
                for (int fn = 0; fn < 4; fn++)
                    mma_tf32(acc[fm][fn], afr[fm], bfr[fn]);
        }
        if (kt + 1 < kt1) {
            int nxt = (kt + 1 - kt0) & 1;
            float* pa = &As[nxt][srow][sc8];
            pa[0] = __uint_as_float(f2tf32(ra0.x)); pa[2] = __uint_as_float(f2tf32(ra0.y));
            pa[4] = __uint_as_float(f2tf32(ra0.z)); pa[6] = __uint_as_float(f2tf32(ra0.w));
            pa[1] = __uint_as_float(f2tf32(ra1.x)); pa[3] = __uint_as_float(f2tf32(ra1.y));
            pa[5] = __uint_as_float(f2tf32(ra1.z)); pa[7] = __uint_as_float(f2tf32(ra1.w));
            float* pw = &Ws[nxt][srow][sc8];
            pw[0] = __uint_as_float(f2tf32(rw0.x)); pw[2] = __uint_as_float(f2tf32(rw0.y));
            pw[4] = __uint_as_float(f2tf32(rw0.z)); pw[6] = __uint_as_float(f2tf32(rw0.w));
            pw[1] = __uint_as_float(f2tf32(rw1.x)); pw[3] = __uint_as_float(f2tf32(rw1.y));
            pw[5] = __uint_as_float(f2tf32(rw1.z)); pw[7] = __uint_as_float(f2tf32(rw1.w));
            __syncthreads();
        }
    }

    // ---- epilogue ----
    bool do_atomic = (ksplit > 1);
    #pragma unroll
    for (int fm = 0; fm < 2; fm++) {
        #pragma unroll
        for (int fn = 0; fn < 4; fn++) {
            #pragma unroll
            for (int half = 0; half < 2; half++) {
                int m = m0 + wm*32 + fm*16 + qr + half*8;
                int ncol = n0 + wn*32 + fn*8 + qc*2;
                if (m >= M || ncol >= N) continue;
                float v0 = acc[fm][fn][half*2];
                float v1 = acc[fm][fn][half*2 + 1];
                if (do_atomic) {
                    atomicAdd(Cp + (long)m*ldc + ncol,     v0);
                    atomicAdd(Cp + (long)m*ldc + ncol + 1, v1);
                } else {
                    if (bp) { v0 += bp[ncol]; v1 += bp[ncol + 1]; }
                    if (act == 2) {
                        v0 = (v0 > 15.0f) ? v0 : log1pf(__expf(v0));
                        v1 = (v1 > 15.0f) ? v1 : log1pf(__expf(v1));
                    }
                    *(float2*)(Cp + (long)m*ldc + ncol) = make_float2(v0, v1);
                }
            }
        }
    }
}

// ---------------- residual accumulate + layernorm: warp per row, float4 ----------------
__global__ void resln_kernel(const float* __restrict__ lw, const float* __restrict__ lb,
                             const float* __restrict__ cls, const float* __restrict__ pos,
                             int first) {
    int row = blockIdx.x * 4 + (threadIdx.x >> 5);
    if (row >= MSEQ) return;
    int lane = threadIdx.x & 31;
    long base = (long)row * D;

    float4 v[3];
    float s = 0.f, q = 0.f;
    if (first) {
        int b = row / Lseq, l = row % Lseq;
        const float* src;
        if (l < POS)       src = g_tok + ((long)b*NTOK + l)*D;
        else if (l == POS) src = cls;
        else               src = g_tok + ((long)b*NTOK + l - 1)*D;
        #pragma unroll
        for (int j = 0; j < 3; j++) {
            int d0 = (lane + j*32) * 4;
            float4 t = *(const float4*)(src + d0);
            float4 pe = *(const float4*)(pos + (long)l*D + d0);
            t.x += pe.x; t.y += pe.y; t.z += pe.z; t.w += pe.w;
            v[j] = t;
            s += t.x + t.y + t.z + t.w;
            q += t.x*t.x + t.y*t.y + t.z*t.z + t.w*t.w;
        }
    } else {
        #pragma unroll
        for (int j = 0; j < 3; j++) {
            int d0 = (lane + j*32) * 4;
            float4 t = *(const float4*)(&g_hidden[base + d0]);
            float4 r = *(const float4*)(&g_resid[base + d0]);
            t.x += r.x; t.y += r.y; t.z += r.z; t.w += r.w;
            v[j] = t;
            s += t.x + t.y + t.z + t.w;
            q += t.x*t.x + t.y*t.y + t.z*t.z + t.w*t.w;
        }
    }
    #pragma unroll
    for (int o = 16; o > 0; o >>= 1) {
        s += __shfl_xor_sync(~0u, s, o);
        q += __shfl_xor_sync(~0u, q, o);
    }
    float mean = s / D;
    float rstd = rsqrtf(q / D - mean*mean + 1e-5f);
    #pragma unroll
    for (int j = 0; j < 3; j++) {
        int d0 = (lane + j*32) * 4;
        *(float4*)(&g_resid[base + d0]) = v[j];
        float4 wv = *(const float4*)(lw + d0);
        float4 bv = *(const float4*)(lb + d0);
        float4 o;
        o.x = (v[j].x - mean)*rstd*wv.x + bv.x;
        o.y = (v[j].y - mean)*rstd*wv.y + bv.y;
        o.z = (v[j].z - mean)*rstd*wv.z + bv.z;
        o.w = (v[j].w - mean)*rstd*wv.w + bv.w;
        *(float4*)(&g_hn[base + d0]) = o;
    }
}

// ---------------- causal conv (K=4) + silu, both branches (float4) ----------------
// Also zeroes split-K accumulation targets: g_xdb row (per br) and g_hidden row (br==0).
__global__ void conv_kernel(const float* __restrict__ cw,  const float* __restrict__ cb,
                            const float* __restrict__ cwb, const float* __restrict__ cbb)
{
    int row = blockIdx.x;       // b*L + l
    int br  = blockIdx.y;
    int b = row / Lseq, l = row % Lseq;

    if (threadIdx.x < XDBE)
        g_xdb[br][(long)row*XDBE + threadIdx.x] = 0.0f;
    if (br == 0)
        *(float2*)(&g_hidden[(long)row*D + threadIdx.x*2]) = make_float2(0.f, 0.f);

    const float* w  = br ? cwb : cw;
    const float* bb = br ? cbb : cb;
    int d0 = threadIdx.x * 4;   // blockDim = 192
    if (d0 >= DIN) return;

    float4 wv[4];
    #pragma unroll
    for (int j = 0; j < 4; j++) wv[j] = *(const float4*)(w + (d0 + j)*4);
    float4 acc = *(const float4*)(bb + d0);

    #pragma unroll
    for (int k = 0; k < 4; k++) {
        int li = l - 3 + k;
        if (li >= 0) {
            int lsrc = br ? (Lseq - 1 - li) : li;
            float4 x = *(const float4*)(&g_xz[((long)b*Lseq + lsrc)*(2*DIN) + d0]);
            acc.x = fmaf(x.x, ((const float*)&wv[0])[k], acc.x);
            acc.y = fmaf(x.y, ((const float*)&wv[1])[k], acc.y);
            acc.z = fmaf(x.z, ((const float*)&wv[2])[k], acc.z);
            acc.w = fmaf(x.w, ((const float*)&wv[3])[k], acc.w);
        }
    }
    float4 o;
    o.x = silu_f(acc.x); o.y = silu_f(acc.y);
    o.z = silu_f(acc.z); o.w = silu_f(acc.w);
    *(float4*)(&g_xc[br][((long)b*Lseq + l)*DIN + d0]) = o;
}

// ---------------- SSM chunked scan pass 1: per-chunk (hB, P) with zero init ----------------
__global__ void ssm_pass1(const float* __restrict__ Alog0, const float* __restrict__ Alog1)
{
    int br = blockIdx.z, b = blockIdx.y;
    int tid = threadIdx.x;            // 128 = 16 d x 8 n-pairs
    int n2 = tid & 7;
    int c = blockIdx.x & (NCH - 1);
    int d = (blockIdx.x >> 3) * 16 + (tid >> 3);

    const float* Alog = br ? Alog1 : Alog0;
    float2 Ac = *(const float2*)(Alog + d*Nst + 2*n2);
    float A0 = -__expf(Ac.x), A1 = -__expf(Ac.y);

    const float* dt_p  = g_dt[br]  + (long)b*Lseq*DIN + d;
    const float* xc_p  = g_xc[br]  + (long)b*Lseq*DIN + d;
    const float* xdb_p = g_xdb[br] + (long)b*Lseq*XDBE;

    int l0 = c * CS;
    int l1 = l0 + CS; if (l1 > Lseq) l1 = Lseq;

    float h0 = 0.f, h1 = 0.f, P0 = 1.f, P1 = 1.f;
    for (int l = l0; l < l1; l++) {
        float dtv = dt_p[(long)l*DIN];
        float xcv = xc_p[(long)l*DIN];
        float2 Bv = *(const float2*)(xdb_p + l*XDBE + DTR + 2*n2);
        float e0 = __expf(dtv * A0);
        float e1 = __expf(dtv * A1);
        float dx = dtv * xcv;
        h0 = fmaf(e0, h0, dx * Bv.x);
        h1 = fmaf(e1, h1, dx * Bv.y);
        P0 *= e0; P1 *= e1;
    }
    g_cs[br][b][c][d][2*n2]     = make_float2(h0, P0);
    g_cs[br][b][c][d][2*n2 + 1] = make_float2(h1, P1);
}

// ---------------- SSM chunked scan pass 2: combine chunk states, rescan, emit y ----------------
__global__ void ssm_pass2(const float* __restrict__ Alog0, const float* __restrict__ Alog1,
                          const float* __restrict__ Dp0,   const float* __restrict__ Dp1)
{
    int br = blockIdx.z, b = blockIdx.y;
    int tid = threadIdx.x;
    int n2 = tid & 7;
    int c = blockIdx.x & (NCH - 1);
    int d = (blockIdx.x >> 3) * 16 + (tid >> 3);

    const float* Alog = br ? Alog1 : Alog0;
    float2 Ac = *(const float2*)(Alog + d*Nst + 2*n2);
    float A0 = -__expf(Ac.x), A1 = -__expf(Ac.y);
    float Dv = (br ? Dp1 : Dp0)[d];

    const float* dt_p  = g_dt[br]  + (long)b*Lseq*DIN + d;
    const float* xc_p  = g_xc[br]  + (long)b*Lseq*DIN + d;
    const float* xdb_p = g_xdb[br] + (long)b*Lseq*XDBE;
    float*       y_p   = g_y[br]   + (long)b*Lseq*DIN + d;
    const float* z_p   = g_xz + (long)b*Lseq*(2*DIN) + DIN + d;

    // combine states of chunks 0..c-1 (exact linear-recurrence composition)
    float h0 = 0.f, h1 = 0.f;
    for (int j = 0; j < c; j++) {
        float2 s0 = g_cs[br][b][j][d][2*n2];
        float2 s1 = g_cs[br][b][j][d][2*n2 + 1];
        h0 = fmaf(s0.y, h0, s0.x);
        h1 = fmaf(s1.y, h1, s1.x);
    }

    int l0 = c * CS;
    int l1 = l0 + CS; if (l1 > Lseq) l1 = Lseq;

    for (int l = l0; l < l1; l++) {
        float dtv = dt_p[(long)l*DIN];
        float xcv = xc_p[(long)l*DIN];
        float2 Bv = *(const float2*)(xdb_p + l*XDBE + DTR + 2*n2);
        float2 Cv = *(const float2*)(xdb_p + l*XDBE + DTR + Nst + 2*n2);
        float e0 = __expf(dtv * A0);
        float e1 = __expf(dtv * A1);
        float dx = dtv * xcv;
        h0 = fmaf(e0, h0, dx * Bv.x);
        h1 = fmaf(e1, h1, dx * Bv.y);
        float p = h0 * Cv.x + h1 * Cv.y;
        p += __shfl_xor_sync(~0u, p, 4);
        p += __shfl_xor_sync(~0u, p, 2);
        p += __shfl_xor_sync(~0u, p, 1);
        if (n2 == 0) {
            int lz = br ? (Lseq - 1 - l) : l;
            float zv = z_p[(long)lz*(2*DIN)];
            y_p[(long)l*DIN] = (p + xcv * Dv) * silu_f(zv);
        }
    }
}

// ---------------- final: residual + LN at POS + cmd MLP ----------------
__global__ void final_kernel(const float* __restrict__ state_vec, const float* __restrict__ action,
                             const float* __restrict__ lnf_w, const float* __restrict__ lnf_b,
                             const float* __restrict__ cw1, const float* __restrict__ cb1,
                             const float* __restrict__ cw2, const float* __restrict__ cb2,
                             float* __restrict__ out)
{
    int b = blockIdx.x, t = threadIdx.x;    // 384 threads
    long off = ((long)b*Lseq + POS)*D + t;
    float v = g_hidden[off] + g_resid[off];

    float s = v, q = v*v;
    #pragma unroll
    for (int o = 16; o > 0; o >>= 1) {
        s += __shfl_xor_sync(~0u, s, o);
        q += __shfl_xor_sync(~0u, q, o);
    }
    __shared__ float rs[12], rq[12];
    __shared__ float s_mean, s_rstd;
    __shared__ float s_cmd[20];
    __shared__ float s_r1[D];
    int w = t >> 5, ln = t & 31;
    if (ln == 0) { rs[w] = s; rq[w] = q; }
    __syncthreads();
    if (t == 0) {
        float ss = 0.f, qq = 0.f;
        #pragma unroll
        for (int i = 0; i < 12; i++) { ss += rs[i]; qq += rq[i]; }
        float m = ss / D;
        s_mean = m;
        s_rstd = rsqrtf(qq / D - m*m + 1e-5f);
    }
    if (t < 16)      s_cmd[t] = state_vec[b*16 + t];
    else if (t < 20) s_cmd[t] = action[b*4 + t - 16];
    __syncthreads();

    float h = (v - s_mean) * s_rstd * lnf_w[t] + lnf_b[t];

    float r1 = cb1[t];
    #pragma unroll
    for (int j = 0; j < 20; j++) r1 = fmaf(s_cmd[j], cw1[t*20 + j], r1);
    s_r1[t] = fmaxf(r1, 0.0f);
    __syncthreads();

    float o2 = cb2[t];
    for (int e = 0; e < D; e++) o2 = fmaf(s_r1[e], cw2[t*D + e], o2);
    out[b*D + t] = h + o2;
}

// ---------------- host launcher ----------------
extern "C" void kernel_launch(void* const* d_in, const int* in_sizes, int n_in,
                              void* d_out, int out_size)
{
    const float* depth_seq = (const float*)d_in[0];
    const float* state_vec = (const float*)d_in[1];
    const float* action    = (const float*)d_in[2];
    const float* patch_w   = (const float*)d_in[3];
    const float* patch_b   = (const float*)d_in[4];
    const float* cls_token = (const float*)d_in[5];
    const float* pos_embed = (const float*)d_in[6];
    const float* ln_w      = (const float*)d_in[7];
    const float* ln_b      = (const float*)d_in[8];
    const float* in_proj_w = (const float*)d_in[9];
    const float* conv_w    = (const float*)d_in[10];
    const float* conv_b    = (const float*)d_in[11];
    const float* conv_wb   = (const float*)d_in[12];
    const float* conv_bb   = (const float*)d_in[13];
    const float* xproj_w   = (const float*)d_in[14];
    const float* xproj_wb  = (const float*)d_in[15];
    const float* dtproj_w  = (const float*)d_in[16];
    const float* dtproj_b  = (const float*)d_in[17];
    const float* dtproj_wb = (const float*)d_in[18];
    const float* dtproj_bb = (const float*)d_in[19];
    const float* A_log     = (const float*)d_in[20];
    const float* A_logb    = (const float*)d_in[21];
    const float* Dp        = (const float*)d_in[22];
    const float* Dpb       = (const float*)d_in[23];
    const float* out_w     = (const float*)d_in[24];
    const float* lnf_w     = (const float*)d_in[25];
    const float* lnf_b     = (const float*)d_in[26];
    const float* cw1       = (const float*)d_in[27];
    const float* cb1       = (const float*)d_in[28];
    const float* cw2       = (const float*)d_in[29];
    const float* cb2       = (const float*)d_in[30];
    float* out = (float*)d_out;

    float *p_xr, *p_tok, *p_hn, *p_xz, *p_xc, *p_xdb, *p_y0, *p_y1, *p_hidden, *p_dt;
    cudaGetSymbolAddress((void**)&p_xr,     g_xr);
    cudaGetSymbolAddress((void**)&p_tok,    g_tok);
    cudaGetSymbolAddress((void**)&p_hn,     g_hn);
    cudaGetSymbolAddress((void**)&p_xz,     g_xz);
    cudaGetSymbolAddress((void**)&p_xc,     g_xc);
    cudaGetSymbolAddress((void**)&p_xdb,    g_xdb);
    cudaGetSymbolAddress((void**)&p_hidden, g_hidden);
    cudaGetSymbolAddress((void**)&p_dt,     g_dt);
    {
        float* base;
        cudaGetSymbolAddress((void**)&base, g_y);
        p_y0 = base;
        p_y1 = base + (long)Bc*Lseq*DIN;
    }

    // 1) patchify + patch-embed GEMM (ks=1, bias)
    patchify_kernel<<<(Bc*NTOK*256 + 255)/256, 256>>>(depth_seq);
    {
        dim3 g(D/64, (Bc*NTOK)/64, 1);
        mma_gemm_kernel<<<g, 128>>>(p_xr, nullptr, patch_w, nullptr, patch_b, nullptr,
                                    p_tok, Bc*NTOK, D, 256, 256, D, 0, 0, 0, 1);
    }

    // 2) layers
    for (int i = 0; i < DEPTH; i++) {
        resln_kernel<<<(MSEQ + 3)/4, 128>>>(ln_w + i*D, ln_b + i*D, cls_token, pos_embed, i == 0);

        {   // in_proj: (1028,384) @ (1536,384)^T -> g_xz  (ks=1: big output, no atomics)
            dim3 g((2*DIN)/64, (MSEQ + 63)/64, 1);
            mma_gemm_kernel<<<g, 128>>>(p_hn, nullptr, in_proj_w + (long)i*2*DIN*D, nullptr,
                                        nullptr, nullptr, p_xz,
                                        MSEQ, 2*DIN, D, D, 2*DIN, 0, 0, 0, 1);
        }

        {   // conv + zero xdb/hidden rows for split-K accumulation
            dim3 g(MSEQ, 2);
            conv_kernel<<<g, 192>>>(conv_w + i*DIN*4, conv_b + i*DIN,
                                    conv_wb + i*DIN*4, conv_bb + i*DIN);
        }

        {   // xproj both branches, split-K x4 (tiny output -> cheap atomics)
            dim3 g(1, (MSEQ + 63)/64, 2*4);
            mma_gemm_kernel<<<g, 128>>>(p_xc, nullptr,
                                        xproj_w + (long)i*XDBE*DIN, xproj_wb + (long)i*XDBE*DIN,
                                        nullptr, nullptr, p_xdb,
                                        MSEQ, XDBE, DIN, DIN, XDBE,
                                        (long)Bc*Lseq*DIN, (long)Bc*Lseq*XDBE, 0, 4);
        }

        {   // dtproj both branches, softplus (ks=1)
            dim3 g(DIN/64, (MSEQ + 63)/64, 2);
            mma_gemm_kernel<<<g, 128>>>(p_xdb, nullptr,
                                        dtproj_w + (long)i*DIN*DTR, dtproj_wb + (long)i*DIN*DTR,
                                        dtproj_b + i*DIN, dtproj_bb + i*DIN, p_dt,
                                        MSEQ, DIN, DTR, XDBE, DIN,
                                        (long)Bc*Lseq*XDBE, (long)Bc*Lseq*DIN, 2, 1);
        }

        {   // chunked SSM scan: pass1 (per-chunk states) + pass2 (combine + emit y)
            dim3 g((DIN/16)*NCH, Bc, 2);
            ssm_pass1<<<g, 128>>>(A_log + (long)i*DIN*Nst, A_logb + (long)i*DIN*Nst);
            ssm_pass2<<<g, 128>>>(A_log + (long)i*DIN*Nst, A_logb + (long)i*DIN*Nst,
                                  Dp + i*DIN, Dpb + i*DIN);
        }

        {   // out_proj, combine fused (A = y0[m] + y1[flip(m)]), split-K x2
            dim3 g(D/64, (MSEQ + 63)/64, 2);
            mma_gemm_kernel<<<g, 128>>>(p_y0, p_y1, out_w + (long)i*D*DIN, nullptr,
                                        nullptr, nullptr, p_hidden,
                                        MSEQ, D, DIN, DIN, D, 0, 0, 0, 2);
        }
    }

    // 3) final LN at POS + command MLP
    final_kernel<<<Bc, D>>>(state_vec, action, lnf_w, lnf_b, cw1, cb1, cw2, cb2, out);
}

// round 15
// speedup vs baseline: 1.4202x; 1.0417x over previous
#include <cuda_runtime.h>
#include <math.h>
#include <stdint.h>

// ---------------- problem constants ----------------
#define Bc    4
#define Tt    4
#define Hh    128
#define Wd    128
#define D     384
#define DEPTH 4
#define DIN   768
#define Nst   16
#define DTR   24
#define NTOK  256
#define Lseq  257
#define POS   128
#define XDBE  56          // DTR + 2N
#define GWp   8           // W/P
#define MSEQ  (Bc*Lseq)   // 1028
#define NCH   8           // scan chunks
#define CS    33          // chunk size (8*33 = 264 >= 257)

// ---------------- scratch (device globals; no allocation allowed) ----------------
__device__ float g_xr[Bc*NTOK*256];
__device__ float g_tok[Bc*NTOK*D];
__device__ float g_resid[Bc*Lseq*D];
__device__ float g_hidden[Bc*Lseq*D];
__device__ float g_hn[Bc*Lseq*D];
__device__ float g_xz[Bc*Lseq*2*DIN];
__device__ float g_xc[2][Bc*Lseq*DIN];
__device__ float g_xdb[2][Bc*Lseq*XDBE];
__device__ float g_dt[2][Bc*Lseq*DIN];
__device__ float g_y[2][Bc*Lseq*DIN];
__device__ float2 g_cs[2][Bc][NCH][DIN][Nst];   // per-chunk (hB, P)

__device__ __forceinline__ float silu_f(float v) {
    return v / (1.0f + __expf(-v));
}

__device__ __forceinline__ uint32_t f2tf32(float v) {
    uint32_t o;
    asm("cvt.rna.tf32.f32 %0, %1;" : "=r"(o) : "f"(v));
    return o;
}

__device__ __forceinline__ void mma_tf32(float* c, const uint32_t* a, const uint32_t* b) {
    asm volatile(
        "mma.sync.aligned.m16n8k8.row.col.f32.tf32.tf32.f32 "
        "{%0,%1,%2,%3}, {%4,%5,%6,%7}, {%8,%9}, {%0,%1,%2,%3};"
        : "+f"(c[0]), "+f"(c[1]), "+f"(c[2]), "+f"(c[3])
        : "r"(a[0]), "r"(a[1]), "r"(a[2]), "r"(a[3]),
          "r"(b[0]), "r"(b[1]));
}

// ---------------- patchify: depth_seq -> xr (B, NTOK, 256) ----------------
__global__ void patchify_kernel(const float* __restrict__ depth) {
    int idx = blockIdx.x * blockDim.x + threadIdx.x;
    if (idx >= Bc*NTOK*256) return;
    int j   = idx & 255;
    int tok = (idx >> 8) % NTOK;
    int b   = idx / (256*NTOK);
    int p2 = j & 15, p1 = j >> 4;
    int gw = tok % GWp, gh = tok / GWp;
    int y = gh*16 + p1, x = gw*16 + p2;
    g_xr[idx] = depth[((long)b*(Tt*Hh) + y)*Wd + x];
}

// ============ tensor-core tf32 GEMM: C (+)= act((A[m] + A2flip[flip(m)]) @ W^T + bias) ============
// 64x64 block tile, BK=16, 256 threads = 8 warps in a 2x4 grid, warp tile 32x16
// (pure spatial split, no reduction). Double-buffered.
// Permuted smem layout within each 8-k chunk: a lane's (k, k+4) pair is one float2.
// ksplit > 1: grid.z = Zbr*ksplit, each slice covers nk/ksplit k-tiles, epilogue atomicAdd.
#define GSTR 18     // 16 + 2 pad (floats)

__global__ __launch_bounds__(256) void mma_gemm_kernel(
    const float* __restrict__ A, const float* __restrict__ A2flip,
    const float* __restrict__ W0, const float* __restrict__ W1,
    const float* __restrict__ bias0, const float* __restrict__ bias1,
    float* __restrict__ C,
    int M, int N, int K, int lda, int ldc,
    long strideA, long strideC, int act, int ksplit)
{
    __shared__ float As[2][64][GSTR];
    __shared__ float Ws[2][64][GSTR];

    int z = blockIdx.z;
    int br = z / ksplit;
    int ks = z - br * ksplit;

    const float* Ap = A + (long)br * strideA;
    const float* Wp = br ? W1 : W0;
    const float* bp = br ? bias1 : bias0;
    float* Cp = C + (long)br * strideC;

    int tid  = threadIdx.x;
    int warp = tid >> 5, lane = tid & 31;
    int wm = warp >> 2, wn = warp & 3;      // 2 x 4 warps, warp tile 32x16
    int qr = lane >> 2, qc = lane & 3;
    int m0 = blockIdx.y * 64, n0 = blockIdx.x * 64;

    // staging: 256 threads, each stages one A float4 and one W float4 per tile
    int srow = tid >> 2;           // 0..63
    int sc4  = (tid & 3) * 4;      // 0,4,8,12
    int spos = (sc4 & 8) + ((sc4 >> 2) & 1);   // permuted base, stride-2 stores

    int am = m0 + srow;
    bool amok = (am < M);
    long aoff = (long)am * lda;
    long a2off = 0;
    if (A2flip) {
        int bb = am / Lseq, ll = am % Lseq;
        a2off = ((long)bb * Lseq + (Lseq - 1 - ll)) * lda;
    }
    int wrow = n0 + srow;
    bool wok = (wrow < N);
    long woff = (long)wrow * K;

    float acc[2][2][4];
    #pragma unroll
    for (int i = 0; i < 2; i++)
        #pragma unroll
        for (int j = 0; j < 2; j++)
            #pragma unroll
            for (int q = 0; q < 4; q++) acc[i][j][q] = 0.0f;

    int nk_total = (K + 15) / 16;
    int nk_s = nk_total / ksplit;
    int kt0 = ks * nk_s, kt1 = kt0 + nk_s;

    const float4 zero4 = make_float4(0.f, 0.f, 0.f, 0.f);
    float4 ra, rw;

    const float* paB[2] = { &As[0][wm*32 + qr][qc*2], &As[1][wm*32 + qr][qc*2] };
    const float* pwB[2] = { &Ws[0][wn*16 + qr][qc*2], &Ws[1][wn*16 + qr][qc*2] };

    // ---- prologue: load tile kt0 ----
    {
        int k = kt0 * 16 + sc4;
        bool kok = (k < K);
        ra = (amok && kok) ? *(const float4*)(Ap + aoff + k) : zero4;
        if (A2flip && amok && kok) {
            float4 t = *(const float4*)(A2flip + a2off + k);
            ra.x += t.x; ra.y += t.y; ra.z += t.z; ra.w += t.w;
        }
        rw = (wok && kok) ? *(const float4*)(Wp + woff + k) : zero4;
    }
    {
        float* pa = &As[0][srow][spos];
        pa[0] = __uint_as_float(f2tf32(ra.x)); pa[2] = __uint_as_float(f2tf32(ra.y));
        pa[4] = __uint_as_float(f2tf32(ra.z)); pa[6] = __uint_as_float(f2tf32(ra.w));
        float* pw = &Ws[0][srow][spos];
        pw[0] = __uint_as_float(f2tf32(rw.x)); pw[2] = __uint_as_float(f2tf32(rw.y));
        pw[4] = __uint_as_float(f2tf32(rw.z)); pw[6] = __uint_as_float(f2tf32(rw.w));
    }
    __syncthreads();

    for (int kt = kt0; kt < kt1; kt++) {
        int cur = (kt - kt0) & 1;
        if (kt + 1 < kt1) {
            int k = (kt + 1) * 16 + sc4;
            bool kok = (k < K);
            ra = (amok && kok) ? *(const float4*)(Ap + aoff + k) : zero4;
            if (A2flip && amok && kok) {
                float4 t = *(const float4*)(A2flip + a2off + k);
                ra.x += t.x; ra.y += t.y; ra.z += t.z; ra.w += t.w;
            }
            rw = (wok && kok) ? *(const float4*)(Wp + woff + k) : zero4;
        }
        // ---- compute tile cur: 2 chunks of 8 k ----
        #pragma unroll
        for (int kk = 0; kk < 2; kk++) {
            int co = kk * 8;
            uint32_t afr[2][4];
            #pragma unroll
            for (int fm = 0; fm < 2; fm++) {
                const float* pa = paB[cur] + fm*16*GSTR + co;
                float2 lo = *(const float2*)pa;
                float2 hi = *(const float2*)(pa + 8*GSTR);
                afr[fm][0] = __float_as_uint(lo.x);
                afr[fm][1] = __float_as_uint(hi.x);
                afr[fm][2] = __float_as_uint(lo.y);
                afr[fm][3] = __float_as_uint(hi.y);
            }
            uint32_t bfr[2][2];
            #pragma unroll
            for (int fn = 0; fn < 2; fn++) {
                float2 bb = *(const float2*)(pwB[cur] + fn*8*GSTR + co);
                bfr[fn][0] = __float_as_uint(bb.x);
                bfr[fn][1] = __float_as_uint(bb.y);
            }
            #pragma unroll
            for (int fm = 0; fm < 2; fm++)
                #pragma unroll
                for (int fn = 0; fn < 2; fn++)
                    mma_tf32(acc[fm][fn], afr[fm], bfr[fn]);
        }
        if (kt + 1 < kt1) {
            int nxt = (kt + 1 - kt0) & 1;
            float* pa = &As[nxt][srow][spos];
            pa[0] = __uint_as_float(f2tf32(ra.x)); pa[2] = __uint_as_float(f2tf32(ra.y));
            pa[4] = __uint_as_float(f2tf32(ra.z)); pa[6] = __uint_as_float(f2tf32(ra.w));
            float* pw = &Ws[nxt][srow][spos];
            pw[0] = __uint_as_float(f2tf32(rw.x)); pw[2] = __uint_as_float(f2tf32(rw.y));
            pw[4] = __uint_as_float(f2tf32(rw.z)); pw[6] = __uint_as_float(f2tf32(rw.w));
            __syncthreads();
        }
    }

    // ---- epilogue ----
    bool do_atomic = (ksplit > 1);
    #pragma unroll
    for (int fm = 0; fm < 2; fm++) {
        #pragma unroll
        for (int fn = 0; fn < 2; fn++) {
            #pragma unroll
            for (int half = 0; half < 2; half++) {
                int m = m0 + wm*32 + fm*16 + qr + half*8;
                int ncol = n0 + wn*16 + fn*8 + qc*2;
                if (m >= M || ncol >= N) continue;
                float v0 = acc[fm][fn][half*2];
                float v1 = acc[fm][fn][half*2 + 1];
                if (do_atomic) {
                    atomicAdd(Cp + (long)m*ldc + ncol,     v0);
                    atomicAdd(Cp + (long)m*ldc + ncol + 1, v1);
                } else {
                    if (bp) { v0 += bp[ncol]; v1 += bp[ncol + 1]; }
                    if (act == 2) {
                        v0 = (v0 > 15.0f) ? v0 : log1pf(__expf(v0));
                        v1 = (v1 > 15.0f) ? v1 : log1pf(__expf(v1));
                    }
                    *(float2*)(Cp + (long)m*ldc + ncol) = make_float2(v0, v1);
                }
            }
        }
    }
}

// ---------------- residual accumulate + layernorm: warp per row, float4 ----------------
__global__ void resln_kernel(const float* __restrict__ lw, const float* __restrict__ lb,
                             const float* __restrict__ cls, const float* __restrict__ pos,
                             int first) {
    int row = blockIdx.x * 4 + (threadIdx.x >> 5);
    if (row >= MSEQ) return;
    int lane = threadIdx.x & 31;
    long base = (long)row * D;

    float4 v[3];
    float s = 0.f, q = 0.f;
    if (first) {
        int b = row / Lseq, l = row % Lseq;
        const float* src;
        if (l < POS)       src = g_tok + ((long)b*NTOK + l)*D;
        else if (l == POS) src = cls;
        else               src = g_tok + ((long)b*NTOK + l - 1)*D;
        #pragma unroll
        for (int j = 0; j < 3; j++) {
            int d0 = (lane + j*32) * 4;
            float4 t = *(const float4*)(src + d0);
            float4 pe = *(const float4*)(pos + (long)l*D + d0);
            t.x += pe.x; t.y += pe.y; t.z += pe.z; t.w += pe.w;
            v[j] = t;
            s += t.x + t.y + t.z + t.w;
            q += t.x*t.x + t.y*t.y + t.z*t.z + t.w*t.w;
        }
    } else {
        #pragma unroll
        for (int j = 0; j < 3; j++) {
            int d0 = (lane + j*32) * 4;
            float4 t = *(const float4*)(&g_hidden[base + d0]);
            float4 r = *(const float4*)(&g_resid[base + d0]);
            t.x += r.x; t.y += r.y; t.z += r.z; t.w += r.w;
            v[j] = t;
            s += t.x + t.y + t.z + t.w;
            q += t.x*t.x + t.y*t.y + t.z*t.z + t.w*t.w;
        }
    }
    #pragma unroll
    for (int o = 16; o > 0; o >>= 1) {
        s += __shfl_xor_sync(~0u, s, o);
        q += __shfl_xor_sync(~0u, q, o);
    }
    float mean = s / D;
    float rstd = rsqrtf(q / D - mean*mean + 1e-5f);
    #pragma unroll
    for (int j = 0; j < 3; j++) {
        int d0 = (lane + j*32) * 4;
        *(float4*)(&g_resid[base + d0]) = v[j];
        float4 wv = *(const float4*)(lw + d0);
        float4 bv = *(const float4*)(lb + d0);
        float4 o;
        o.x = (v[j].x - mean)*rstd*wv.x + bv.x;
        o.y = (v[j].y - mean)*rstd*wv.y + bv.y;
        o.z = (v[j].z - mean)*rstd*wv.z + bv.z;
        o.w = (v[j].w - mean)*rstd*wv.w + bv.w;
        *(float4*)(&g_hn[base + d0]) = o;
    }
}

// ---------------- causal conv (K=4) + silu, both branches (float4) ----------------
// Also zeroes split-K accumulation targets: g_xdb row (per br) and g_hidden row (br==0).
__global__ void conv_kernel(const float* __restrict__ cw,  const float* __restrict__ cb,
                            const float* __restrict__ cwb, const float* __restrict__ cbb)
{
    int row = blockIdx.x;       // b*L + l
    int br  = blockIdx.y;
    int b = row / Lseq, l = row % Lseq;

    if (threadIdx.x < XDBE)
        g_xdb[br][(long)row*XDBE + threadIdx.x] = 0.0f;
    if (br == 0)
        *(float2*)(&g_hidden[(long)row*D + threadIdx.x*2]) = make_float2(0.f, 0.f);

    const float* w  = br ? cwb : cw;
    const float* bb = br ? cbb : cb;
    int d0 = threadIdx.x * 4;   // blockDim = 192
    if (d0 >= DIN) return;

    float4 wv[4];
    #pragma unroll
    for (int j = 0; j < 4; j++) wv[j] = *(const float4*)(w + (d0 + j)*4);
    float4 acc = *(const float4*)(bb + d0);

    #pragma unroll
    for (int k = 0; k < 4; k++) {
        int li = l - 3 + k;
        if (li >= 0) {
            int lsrc = br ? (Lseq - 1 - li) : li;
            float4 x = *(const float4*)(&g_xz[((long)b*Lseq + lsrc)*(2*DIN) + d0]);
            acc.x = fmaf(x.x, ((const float*)&wv[0])[k], acc.x);
            acc.y = fmaf(x.y, ((const float*)&wv[1])[k], acc.y);
            acc.z = fmaf(x.z, ((const float*)&wv[2])[k], acc.z);
            acc.w = fmaf(x.w, ((const float*)&wv[3])[k], acc.w);
        }
    }
    float4 o;
    o.x = silu_f(acc.x); o.y = silu_f(acc.y);
    o.z = silu_f(acc.z); o.w = silu_f(acc.w);
    *(float4*)(&g_xc[br][((long)b*Lseq + l)*DIN + d0]) = o;
}

// ---------------- SSM chunked scan pass 1: per-chunk (hB, P) with zero init ----------------
__global__ void ssm_pass1(const float* __restrict__ Alog0, const float* __restrict__ Alog1)
{
    int br = blockIdx.z, b = blockIdx.y;
    int tid = threadIdx.x;            // 128 = 16 d x 8 n-pairs
    int n2 = tid & 7;
    int c = blockIdx.x & (NCH - 1);
    int d = (blockIdx.x >> 3) * 16 + (tid >> 3);

    const float* Alog = br ? Alog1 : Alog0;
    float2 Ac = *(const float2*)(Alog + d*Nst + 2*n2);
    float A0 = -__expf(Ac.x), A1 = -__expf(Ac.y);

    const float* dt_p  = g_dt[br]  + (long)b*Lseq*DIN + d;
    const float* xc_p  = g_xc[br]  + (long)b*Lseq*DIN + d;
    const float* xdb_p = g_xdb[br] + (long)b*Lseq*XDBE;

    int l0 = c * CS;
    int l1 = l0 + CS; if (l1 > Lseq) l1 = Lseq;

    float h0 = 0.f, h1 = 0.f, P0 = 1.f, P1 = 1.f;
    for (int l = l0; l < l1; l++) {
        float dtv = dt_p[(long)l*DIN];
        float xcv = xc_p[(long)l*DIN];
        float2 Bv = *(const float2*)(xdb_p + l*XDBE + DTR + 2*n2);
        float e0 = __expf(dtv * A0);
        float e1 = __expf(dtv * A1);
        float dx = dtv * xcv;
        h0 = fmaf(e0, h0, dx * Bv.x);
        h1 = fmaf(e1, h1, dx * Bv.y);
        P0 *= e0; P1 *= e1;
    }
    g_cs[br][b][c][d][2*n2]     = make_float2(h0, P0);
    g_cs[br][b][c][d][2*n2 + 1] = make_float2(h1, P1);
}

// ---------------- SSM chunked scan pass 2: combine chunk states, rescan, emit y ----------------
__global__ void ssm_pass2(const float* __restrict__ Alog0, const float* __restrict__ Alog1,
                          const float* __restrict__ Dp0,   const float* __restrict__ Dp1)
{
    int br = blockIdx.z, b = blockIdx.y;
    int tid = threadIdx.x;
    int n2 = tid & 7;
    int c = blockIdx.x & (NCH - 1);
    int d = (blockIdx.x >> 3) * 16 + (tid >> 3);

    const float* Alog = br ? Alog1 : Alog0;
    float2 Ac = *(const float2*)(Alog + d*Nst + 2*n2);
    float A0 = -__expf(Ac.x), A1 = -__expf(Ac.y);
    float Dv = (br ? Dp1 : Dp0)[d];

    const float* dt_p  = g_dt[br]  + (long)b*Lseq*DIN + d;
    const float* xc_p  = g_xc[br]  + (long)b*Lseq*DIN + d;
    const float* xdb_p = g_xdb[br] + (long)b*Lseq*XDBE;
    float*       y_p   = g_y[br]   + (long)b*Lseq*DIN + d;
    const float* z_p   = g_xz + (long)b*Lseq*(2*DIN) + DIN + d;

    // combine states of chunks 0..c-1 (exact linear-recurrence composition)
    float h0 = 0.f, h1 = 0.f;
    for (int j = 0; j < c; j++) {
        float2 s0 = g_cs[br][b][j][d][2*n2];
        float2 s1 = g_cs[br][b][j][d][2*n2 + 1];
        h0 = fmaf(s0.y, h0, s0.x);
        h1 = fmaf(s1.y, h1, s1.x);
    }

    int l0 = c * CS;
    int l1 = l0 + CS; if (l1 > Lseq) l1 = Lseq;

    for (int l = l0; l < l1; l++) {
        float dtv = dt_p[(long)l*DIN];
        float xcv = xc_p[(long)l*DIN];
        float2 Bv = *(const float2*)(xdb_p + l*XDBE + DTR + 2*n2);
        float2 Cv = *(const float2*)(xdb_p + l*XDBE + DTR + Nst + 2*n2);
        float e0 = __expf(dtv * A0);
        float e1 = __expf(dtv * A1);
        float dx = dtv * xcv;
        h0 = fmaf(e0, h0, dx * Bv.x);
        h1 = fmaf(e1, h1, dx * Bv.y);
        float p = h0 * Cv.x + h1 * Cv.y;
        p += __shfl_xor_sync(~0u, p, 4);
        p += __shfl_xor_sync(~0u, p, 2);
        p += __shfl_xor_sync(~0u, p, 1);
        if (n2 == 0) {
            int lz = br ? (Lseq - 1 - l) : l;
            float zv = z_p[(long)lz*(2*DIN)];
            y_p[(long)l*DIN] = (p + xcv * Dv) * silu_f(zv);
        }
    }
}

// ---------------- final: residual + LN at POS + cmd MLP ----------------
__global__ void final_kernel(const float* __restrict__ state_vec, const float* __restrict__ action,
                             const float* __restrict__ lnf_w, const float* __restrict__ lnf_b,
                             const float* __restrict__ cw1, const float* __restrict__ cb1,
                             const float* __restrict__ cw2, const float* __restrict__ cb2,
                             float* __restrict__ out)
{
    int b = blockIdx.x, t = threadIdx.x;    // 384 threads
    long off = ((long)b*Lseq + POS)*D + t;
    float v = g_hidden[off] + g_resid[off];

    float s = v, q = v*v;
    #pragma unroll
    for (int o = 16; o > 0; o >>= 1) {
        s += __shfl_xor_sync(~0u, s, o);
        q += __shfl_xor_sync(~0u, q, o);
    }
    __shared__ float rs[12], rq[12];
    __shared__ float s_mean, s_rstd;
    __shared__ float s_cmd[20];
    __shared__ float s_r1[D];
    int w = t >> 5, ln = t & 31;
    if (ln == 0) { rs[w] = s; rq[w] = q; }
    __syncthreads();
    if (t == 0) {
        float ss = 0.f, qq = 0.f;
        #pragma unroll
        for (int i = 0; i < 12; i++) { ss += rs[i]; qq += rq[i]; }
        float m = ss / D;
        s_mean = m;
        s_rstd = rsqrtf(qq / D - m*m + 1e-5f);
    }
    if (t < 16)      s_cmd[t] = state_vec[b*16 + t];
    else if (t < 20) s_cmd[t] = action[b*4 + t - 16];
    __syncthreads();

    float h = (v - s_mean) * s_rstd * lnf_w[t] + lnf_b[t];

    float r1 = cb1[t];
    #pragma unroll
    for (int j = 0; j < 20; j++) r1 = fmaf(s_cmd[j], cw1[t*20 + j], r1);
    s_r1[t] = fmaxf(r1, 0.0f);
    __syncthreads();

    float o2 = cb2[t];
    for (int e = 0; e < D; e++) o2 = fmaf(s_r1[e], cw2[t*D + e], o2);
    out[b*D + t] = h + o2;
}

// ---------------- host launcher ----------------
extern "C" void kernel_launch(void* const* d_in, const int* in_sizes, int n_in,
                              void* d_out, int out_size)
{
    const float* depth_seq = (const float*)d_in[0];
    const float* state_vec = (const float*)d_in[1];
    const float* action    = (const float*)d_in[2];
    const float* patch_w   = (const float*)d_in[3];
    const float* patch_b   = (const float*)d_in[4];
    const float* cls_token = (const float*)d_in[5];
    const float* pos_embed = (const float*)d_in[6];
    const float* ln_w      = (const float*)d_in[7];
    const float* ln_b      = (const float*)d_in[8];
    const float* in_proj_w = (const float*)d_in[9];
    const float* conv_w    = (const float*)d_in[10];
    const float* conv_b    = (const float*)d_in[11];
    const float* conv_wb   = (const float*)d_in[12];
    const float* conv_bb   = (const float*)d_in[13];
    const float* xproj_w   = (const float*)d_in[14];
    const float* xproj_wb  = (const float*)d_in[15];
    const float* dtproj_w  = (const float*)d_in[16];
    const float* dtproj_b  = (const float*)d_in[17];
    const float* dtproj_wb = (const float*)d_in[18];
    const float* dtproj_bb = (const float*)d_in[19];
    const float* A_log     = (const float*)d_in[20];
    const float* A_logb    = (const float*)d_in[21];
    const float* Dp        = (const float*)d_in[22];
    const float* Dpb       = (const float*)d_in[23];
    const float* out_w     = (const float*)d_in[24];
    const float* lnf_w     = (const float*)d_in[25];
    const float* lnf_b     = (const float*)d_in[26];
    const float* cw1       = (const float*)d_in[27];
    const float* cb1       = (const float*)d_in[28];
    const float* cw2       = (const float*)d_in[29];
    const float* cb2       = (const float*)d_in[30];
    float* out = (float*)d_out;

    float *p_xr, *p_tok, *p_hn, *p_xz, *p_xc, *p_xdb, *p_y0, *p_y1, *p_hidden, *p_dt;
    cudaGetSymbolAddress((void**)&p_xr,     g_xr);
    cudaGetSymbolAddress((void**)&p_tok,    g_tok);
    cudaGetSymbolAddress((void**)&p_hn,     g_hn);
    cudaGetSymbolAddress((void**)&p_xz,     g_xz);
    cudaGetSymbolAddress((void**)&p_xc,     g_xc);
    cudaGetSymbolAddress((void**)&p_xdb,    g_xdb);
    cudaGetSymbolAddress((void**)&p_hidden, g_hidden);
    cudaGetSymbolAddress((void**)&p_dt,     g_dt);
    {
        float* base;
        cudaGetSymbolAddress((void**)&base, g_y);
        p_y0 = base;
        p_y1 = base + (long)Bc*Lseq*DIN;
    }

    // 1) patchify + patch-embed GEMM (ks=1, bias)
    patchify_kernel<<<(Bc*NTOK*256 + 255)/256, 256>>>(depth_seq);
    {
        dim3 g(D/64, (Bc*NTOK)/64, 1);
        mma_gemm_kernel<<<g, 256>>>(p_xr, nullptr, patch_w, nullptr, patch_b, nullptr,
                                    p_tok, Bc*NTOK, D, 256, 256, D, 0, 0, 0, 1);
    }

    // 2) layers
    for (int i = 0; i < DEPTH; i++) {
        resln_kernel<<<(MSEQ + 3)/4, 128>>>(ln_w + i*D, ln_b + i*D, cls_token, pos_embed, i == 0);

        {   // in_proj: (1028,384) @ (1536,384)^T -> g_xz  (ks=1: big output, no atomics)
            dim3 g((2*DIN)/64, (MSEQ + 63)/64, 1);
            mma_gemm_kernel<<<g, 256>>>(p_hn, nullptr, in_proj_w + (long)i*2*DIN*D, nullptr,
                                        nullptr, nullptr, p_xz,
                                        MSEQ, 2*DIN, D, D, 2*DIN, 0, 0, 0, 1);
        }

        {   // conv + zero xdb/hidden rows for split-K accumulation
            dim3 g(MSEQ, 2);
            conv_kernel<<<g, 192>>>(conv_w + i*DIN*4, conv_b + i*DIN,
                                    conv_wb + i*DIN*4, conv_bb + i*DIN);
        }

        {   // xproj both branches, split-K x8 (tiny output -> cheap atomics)
            dim3 g(1, (MSEQ + 63)/64, 2*8);
            mma_gemm_kernel<<<g, 256>>>(p_xc, nullptr,
                                        xproj_w + (long)i*XDBE*DIN, xproj_wb + (long)i*XDBE*DIN,
                                        nullptr, nullptr, p_xdb,
                                        MSEQ, XDBE, DIN, DIN, XDBE,
                                        (long)Bc*Lseq*DIN, (long)Bc*Lseq*XDBE, 0, 8);
        }

        {   // dtproj both branches, softplus (ks=1)
            dim3 g(DIN/64, (MSEQ + 63)/64, 2);
            mma_gemm_kernel<<<g, 256>>>(p_xdb, nullptr,
                                        dtproj_w + (long)i*DIN*DTR, dtproj_wb + (long)i*DIN*DTR,
                                        dtproj_b + i*DIN, dtproj_bb + i*DIN, p_dt,
                                        MSEQ, DIN, DTR, XDBE, DIN,
                                        (long)Bc*Lseq*XDBE, (long)Bc*Lseq*DIN, 2, 1);
        }

        {   // chunked SSM scan: pass1 (per-chunk states) + pass2 (combine + emit y)
            dim3 g((DIN/16)*NCH, Bc, 2);
            ssm_pass1<<<g, 128>>>(A_log + (long)i*DIN*Nst, A_logb + (long)i*DIN*Nst);
            ssm_pass2<<<g, 128>>>(A_log + (long)i*DIN*Nst, A_logb + (long)i*DIN*Nst,
                                  Dp + i*DIN, Dpb + i*DIN);
        }

        {   // out_proj, combine fused (A = y0[m] + y1[flip(m)]), split-K x2
            dim3 g(D/64, (MSEQ + 63)/64, 2);
            mma_gemm_kernel<<<g, 256>>>(p_y0, p_y1, out_w + (long)i*D*DIN, nullptr,
                                        nullptr, nullptr, p_hidden,
                                        MSEQ, D, DIN, DIN, D, 0, 0, 0, 2);
        }
    }

    // 3) final LN at POS + command MLP
    final_kernel<<<Bc, D>>>(state_vec, action, lnf_w, lnf_b, cw1, cb1, cw2, cb2, out);
}

// round 16
// speedup vs baseline: 1.4748x; 1.0384x over previous
#include <cuda_runtime.h>
#include <math.h>
#include <stdint.h>

// ---------------- problem constants ----------------
#define Bc    4
#define Tt    4
#define Hh    128
#define Wd    128
#define D     384
#define DEPTH 4
#define DIN   768
#define Nst   16
#define DTR   24
#define NTOK  256
#define Lseq  257
#define POS   128
#define XDBE  56          // DTR + 2N
#define GWp   8           // W/P
#define MSEQ  (Bc*Lseq)   // 1028
#define NCH   8           // scan chunks
#define CS    33          // chunk size (8*33 = 264 >= 257)

// ---------------- scratch (device globals; no allocation allowed) ----------------
__device__ float g_xr[Bc*NTOK*256];
__device__ float g_tok[Bc*NTOK*D];
__device__ float g_resid[Bc*Lseq*D];
__device__ float g_hidden[Bc*Lseq*D];
__device__ float g_hn[Bc*Lseq*D];
__device__ float g_xz[Bc*Lseq*2*DIN];
__device__ float g_xc[2][Bc*Lseq*DIN];
__device__ float g_xdb[2][Bc*Lseq*XDBE];
__device__ float g_dt[2][Bc*Lseq*DIN];
__device__ float g_y[2][Bc*Lseq*DIN];
__device__ float2 g_cs[2][Bc][NCH][DIN][Nst];   // per-chunk (hB, P)

__device__ __forceinline__ float silu_f(float v) {
    return v / (1.0f + __expf(-v));
}

__device__ __forceinline__ uint32_t f2tf32(float v) {
    uint32_t o;
    asm("cvt.rna.tf32.f32 %0, %1;" : "=r"(o) : "f"(v));
    return o;
}

__device__ __forceinline__ void mma_tf32(float* c, const uint32_t* a, const uint32_t* b) {
    asm volatile(
        "mma.sync.aligned.m16n8k8.row.col.f32.tf32.tf32.f32 "
        "{%0,%1,%2,%3}, {%4,%5,%6,%7}, {%8,%9}, {%0,%1,%2,%3};"
        : "+f"(c[0]), "+f"(c[1]), "+f"(c[2]), "+f"(c[3])
        : "r"(a[0]), "r"(a[1]), "r"(a[2]), "r"(a[3]),
          "r"(b[0]), "r"(b[1]));
}

// ---------------- patchify: depth_seq -> xr (B, NTOK, 256) ----------------
__global__ void patchify_kernel(const float* __restrict__ depth) {
    int idx = blockIdx.x * blockDim.x + threadIdx.x;
    if (idx >= Bc*NTOK*256) return;
    int j   = idx & 255;
    int tok = (idx >> 8) % NTOK;
    int b   = idx / (256*NTOK);
    int p2 = j & 15, p1 = j >> 4;
    int gw = tok % GWp, gh = tok / GWp;
    int y = gh*16 + p1, x = gw*16 + p2;
    g_xr[idx] = depth[((long)b*(Tt*Hh) + y)*Wd + x];
}

// ============ tensor-core tf32 GEMM: C (+)= act((A[m] + A2flip[flip(m)]) @ W^T + bias) ============
// 64x64 block tile, BK=16, 256 threads = 8 warps in a 2x4 grid, warp tile 32x16
// (pure spatial split, no reduction). Double-buffered.
// Permuted smem layout within each 8-k chunk: a lane's (k, k+4) pair is one float2.
// GSTR=24: row starts hit banks {0,24,16,8} per half-warp phase -> LDS.64 fragment
// loads are conflict-free (2-phase floor), unlike GSTR=18 (2-way conflicts).
// ksplit > 1: grid.z = Zbr*ksplit, each slice covers nk/ksplit k-tiles, epilogue atomicAdd.
#define GSTR 24     // 16 + 8 pad (floats)

__global__ __launch_bounds__(256) void mma_gemm_kernel(
    const float* __restrict__ A, const float* __restrict__ A2flip,
    const float* __restrict__ W0, const float* __restrict__ W1,
    const float* __restrict__ bias0, const float* __restrict__ bias1,
    float* __restrict__ C,
    int M, int N, int K, int lda, int ldc,
    long strideA, long strideC, int act, int ksplit)
{
    __shared__ float As[2][64][GSTR];
    __shared__ float Ws[2][64][GSTR];

    int z = blockIdx.z;
    int br = z / ksplit;
    int ks = z - br * ksplit;

    const float* Ap = A + (long)br * strideA;
    const float* Wp = br ? W1 : W0;
    const float* bp = br ? bias1 : bias0;
    float* Cp = C + (long)br * strideC;

    int tid  = threadIdx.x;
    int warp = tid >> 5, lane = tid & 31;
    int wm = warp >> 2, wn = warp & 3;      // 2 x 4 warps, warp tile 32x16
    int qr = lane >> 2, qc = lane & 3;
    int m0 = blockIdx.y * 64, n0 = blockIdx.x * 64;

    // staging: 256 threads, each stages one A float4 and one W float4 per tile
    int srow = tid >> 2;           // 0..63
    int sc4  = (tid & 3) * 4;      // 0,4,8,12
    int spos = (sc4 & 8) + ((sc4 >> 2) & 1);   // permuted base, stride-2 stores

    int am = m0 + srow;
    bool amok = (am < M);
    long aoff = (long)am * lda;
    long a2off = 0;
    if (A2flip) {
        int bb = am / Lseq, ll = am % Lseq;
        a2off = ((long)bb * Lseq + (Lseq - 1 - ll)) * lda;
    }
    int wrow = n0 + srow;
    bool wok = (wrow < N);
    long woff = (long)wrow * K;

    float acc[2][2][4];
    #pragma unroll
    for (int i = 0; i < 2; i++)
        #pragma unroll
        for (int j = 0; j < 2; j++)
            #pragma unroll
            for (int q = 0; q < 4; q++) acc[i][j][q] = 0.0f;

    int nk_total = (K + 15) / 16;
    int nk_s = nk_total / ksplit;
    int kt0 = ks * nk_s, kt1 = kt0 + nk_s;

    const float4 zero4 = make_float4(0.f, 0.f, 0.f, 0.f);
    float4 ra, rw;

    const float* paB[2] = { &As[0][wm*32 + qr][qc*2], &As[1][wm*32 + qr][qc*2] };
    const float* pwB[2] = { &Ws[0][wn*16 + qr][qc*2], &Ws[1][wn*16 + qr][qc*2] };

    // ---- prologue: load tile kt0 ----
    {
        int k = kt0 * 16 + sc4;
        bool kok = (k < K);
        ra = (amok && kok) ? *(const float4*)(Ap + aoff + k) : zero4;
        if (A2flip && amok && kok) {
            float4 t = *(const float4*)(A2flip + a2off + k);
            ra.x += t.x; ra.y += t.y; ra.z += t.z; ra.w += t.w;
        }
        rw = (wok && kok) ? *(const float4*)(Wp + woff + k) : zero4;
    }
    {
        float* pa = &As[0][srow][spos];
        pa[0] = __uint_as_float(f2tf32(ra.x)); pa[2] = __uint_as_float(f2tf32(ra.y));
        pa[4] = __uint_as_float(f2tf32(ra.z)); pa[6] = __uint_as_float(f2tf32(ra.w));
        float* pw = &Ws[0][srow][spos];
        pw[0] = __uint_as_float(f2tf32(rw.x)); pw[2] = __uint_as_float(f2tf32(rw.y));
        pw[4] = __uint_as_float(f2tf32(rw.z)); pw[6] = __uint_as_float(f2tf32(rw.w));
    }
    __syncthreads();

    for (int kt = kt0; kt < kt1; kt++) {
        int cur = (kt - kt0) & 1;
        if (kt + 1 < kt1) {
            int k = (kt + 1) * 16 + sc4;
            bool kok = (k < K);
            ra = (amok && kok) ? *(const float4*)(Ap + aoff + k) : zero4;
            if (A2flip && amok && kok) {
                float4 t = *(const float4*)(A2flip + a2off + k);
                ra.x += t.x; ra.y += t.y; ra.z += t.z; ra.w += t.w;
            }
            rw = (wok && kok) ? *(const float4*)(Wp + woff + k) : zero4;
        }
        // ---- compute tile cur: 2 chunks of 8 k ----
        #pragma unroll
        for (int kk = 0; kk < 2; kk++) {
            int co = kk * 8;
            uint32_t afr[2][4];
            #pragma unroll
            for (int fm = 0; fm < 2; fm++) {
                const float* pa = paB[cur] + fm*16*GSTR + co;
                float2 lo = *(const float2*)pa;
                float2 hi = *(const float2*)(pa + 8*GSTR);
                afr[fm][0] = __float_as_uint(lo.x);
                afr[fm][1] = __float_as_uint(hi.x);
                afr[fm][2] = __float_as_uint(lo.y);
                afr[fm][3] = __float_as_uint(hi.y);
            }
            uint32_t bfr[2][2];
            #pragma unroll
            for (int fn = 0; fn < 2; fn++) {
                float2 bb = *(const float2*)(pwB[cur] + fn*8*GSTR + co);
                bfr[fn][0] = __float_as_uint(bb.x);
                bfr[fn][1] = __float_as_uint(bb.y);
            }
            #pragma unroll
            for (int fm = 0; fm < 2; fm++)
                #pragma unroll
                for (int fn = 0; fn < 2; fn++)
                    mma_tf32(acc[fm][fn], afr[fm], bfr[fn]);
        }
        if (kt + 1 < kt1) {
            int nxt = (kt + 1 - kt0) & 1;
            float* pa = &As[nxt][srow][spos];
            pa[0] = __uint_as_float(f2tf32(ra.x)); pa[2] = __uint_as_float(f2tf32(ra.y));
            pa[4] = __uint_as_float(f2tf32(ra.z)); pa[6] = __uint_as_float(f2tf32(ra.w));
            float* pw = &Ws[nxt][srow][spos];
            pw[0] = __uint_as_float(f2tf32(rw.x)); pw[2] = __uint_as_float(f2tf32(rw.y));
            pw[4] = __uint_as_float(f2tf32(rw.z)); pw[6] = __uint_as_float(f2tf32(rw.w));
            __syncthreads();
        }
    }

    // ---- epilogue ----
    bool do_atomic = (ksplit > 1);
    #pragma unroll
    for (int fm = 0; fm < 2; fm++) {
        #pragma unroll
        for (int fn = 0; fn < 2; fn++) {
            #pragma unroll
            for (int half = 0; half < 2; half++) {
                int m = m0 + wm*32 + fm*16 + qr + half*8;
                int ncol = n0 + wn*16 + fn*8 + qc*2;
                if (m >= M || ncol >= N) continue;
                float v0 = acc[fm][fn][half*2];
                float v1 = acc[fm][fn][half*2 + 1];
                if (do_atomic) {
                    atomicAdd(Cp + (long)m*ldc + ncol,     v0);
                    atomicAdd(Cp + (long)m*ldc + ncol + 1, v1);
                } else {
                    if (bp) { v0 += bp[ncol]; v1 += bp[ncol + 1]; }
                    if (act == 2) {
                        v0 = (v0 > 15.0f) ? v0 : log1pf(__expf(v0));
                        v1 = (v1 > 15.0f) ? v1 : log1pf(__expf(v1));
                    }
                    *(float2*)(Cp + (long)m*ldc + ncol) = make_float2(v0, v1);
                }
            }
        }
    }
}

// ---------------- residual accumulate + layernorm: warp per row, float4 ----------------
__global__ void resln_kernel(const float* __restrict__ lw, const float* __restrict__ lb,
                             const float* __restrict__ cls, const float* __restrict__ pos,
                             int first) {
    int row = blockIdx.x * 4 + (threadIdx.x >> 5);
    if (row >= MSEQ) return;
    int lane = threadIdx.x & 31;
    long base = (long)row * D;

    float4 v[3];
    float s = 0.f, q = 0.f;
    if (first) {
        int b = row / Lseq, l = row % Lseq;
        const float* src;
        if (l < POS)       src = g_tok + ((long)b*NTOK + l)*D;
        else if (l == POS) src = cls;
        else               src = g_tok + ((long)b*NTOK + l - 1)*D;
        #pragma unroll
        for (int j = 0; j < 3; j++) {
            int d0 = (lane + j*32) * 4;
            float4 t = *(const float4*)(src + d0);
            float4 pe = *(const float4*)(pos + (long)l*D + d0);
            t.x += pe.x; t.y += pe.y; t.z += pe.z; t.w += pe.w;
            v[j] = t;
            s += t.x + t.y + t.z + t.w;
            q += t.x*t.x + t.y*t.y + t.z*t.z + t.w*t.w;
        }
    } else {
        #pragma unroll
        for (int j = 0; j < 3; j++) {
            int d0 = (lane + j*32) * 4;
            float4 t = *(const float4*)(&g_hidden[base + d0]);
            float4 r = *(const float4*)(&g_resid[base + d0]);
            t.x += r.x; t.y += r.y; t.z += r.z; t.w += r.w;
            v[j] = t;
            s += t.x + t.y + t.z + t.w;
            q += t.x*t.x + t.y*t.y + t.z*t.z + t.w*t.w;
        }
    }
    #pragma unroll
    for (int o = 16; o > 0; o >>= 1) {
        s += __shfl_xor_sync(~0u, s, o);
        q += __shfl_xor_sync(~0u, q, o);
    }
    float mean = s / D;
    float rstd = rsqrtf(q / D - mean*mean + 1e-5f);
    #pragma unroll
    for (int j = 0; j < 3; j++) {
        int d0 = (lane + j*32) * 4;
        *(float4*)(&g_resid[base + d0]) = v[j];
        float4 wv = *(const float4*)(lw + d0);
        float4 bv = *(const float4*)(lb + d0);
        float4 o;
        o.x = (v[j].x - mean)*rstd*wv.x + bv.x;
        o.y = (v[j].y - mean)*rstd*wv.y + bv.y;
        o.z = (v[j].z - mean)*rstd*wv.z + bv.z;
        o.w = (v[j].w - mean)*rstd*wv.w + bv.w;
        *(float4*)(&g_hn[base + d0]) = o;
    }
}

// ---------------- causal conv (K=4) + silu, both branches (float4) ----------------
// Also zeroes split-K accumulation targets: g_xdb row (per br) and g_hidden row (br==0).
__global__ void conv_kernel(const float* __restrict__ cw,  const float* __restrict__ cb,
                            const float* __restrict__ cwb, const float* __restrict__ cbb)
{
    int row = blockIdx.x;       // b*L + l
    int br  = blockIdx.y;
    int b = row / Lseq, l = row % Lseq;

    if (threadIdx.x < XDBE)
        g_xdb[br][(long)row*XDBE + threadIdx.x] = 0.0f;
    if (br == 0)
        *(float2*)(&g_hidden[(long)row*D + threadIdx.x*2]) = make_float2(0.f, 0.f);

    const float* w  = br ? cwb : cw;
    const float* bb = br ? cbb : cb;
    int d0 = threadIdx.x * 4;   // blockDim = 192
    if (d0 >= DIN) return;

    float4 wv[4];
    #pragma unroll
    for (int j = 0; j < 4; j++) wv[j] = *(const float4*)(w + (d0 + j)*4);
    float4 acc = *(const float4*)(bb + d0);

    #pragma unroll
    for (int k = 0; k < 4; k++) {
        int li = l - 3 + k;
        if (li >= 0) {
            int lsrc = br ? (Lseq - 1 - li) : li;
            float4 x = *(const float4*)(&g_xz[((long)b*Lseq + lsrc)*(2*DIN) + d0]);
            acc.x = fmaf(x.x, ((const float*)&wv[0])[k], acc.x);
            acc.y = fmaf(x.y, ((const float*)&wv[1])[k], acc.y);
            acc.z = fmaf(x.z, ((const float*)&wv[2])[k], acc.z);
            acc.w = fmaf(x.w, ((const float*)&wv[3])[k], acc.w);
        }
    }
    float4 o;
    o.x = silu_f(acc.x); o.y = silu_f(acc.y);
    o.z = silu_f(acc.z); o.w = silu_f(acc.w);
    *(float4*)(&g_xc[br][((long)b*Lseq + l)*DIN + d0]) = o;
}

// ---------------- SSM chunked scan pass 1: per-chunk (hB, P) with zero init ----------------
__global__ void ssm_pass1(const float* __restrict__ Alog0, const float* __restrict__ Alog1)
{
    int br = blockIdx.z, b = blockIdx.y;
    int tid = threadIdx.x;            // 128 = 16 d x 8 n-pairs
    int n2 = tid & 7;
    int c = blockIdx.x & (NCH - 1);
    int d = (blockIdx.x >> 3) * 16 + (tid >> 3);

    const float* Alog = br ? Alog1 : Alog0;
    float2 Ac = *(const float2*)(Alog + d*Nst + 2*n2);
    float A0 = -__expf(Ac.x), A1 = -__expf(Ac.y);

    const float* dt_p  = g_dt[br]  + (long)b*Lseq*DIN + d;
    const float* xc_p  = g_xc[br]  + (long)b*Lseq*DIN + d;
    const float* xdb_p = g_xdb[br] + (long)b*Lseq*XDBE;

    int l0 = c * CS;
    int l1 = l0 + CS; if (l1 > Lseq) l1 = Lseq;

    float h0 = 0.f, h1 = 0.f, P0 = 1.f, P1 = 1.f;
    for (int l = l0; l < l1; l++) {
        float dtv = dt_p[(long)l*DIN];
        float xcv = xc_p[(long)l*DIN];
        float2 Bv = *(const float2*)(xdb_p + l*XDBE + DTR + 2*n2);
        float e0 = __expf(dtv * A0);
        float e1 = __expf(dtv * A1);
        float dx = dtv * xcv;
        h0 = fmaf(e0, h0, dx * Bv.x);
        h1 = fmaf(e1, h1, dx * Bv.y);
        P0 *= e0; P1 *= e1;
    }
    g_cs[br][b][c][d][2*n2]     = make_float2(h0, P0);
    g_cs[br][b][c][d][2*n2 + 1] = make_float2(h1, P1);
}

// ---------------- SSM chunked scan pass 2: combine chunk states, rescan, emit y ----------------
__global__ void ssm_pass2(const float* __restrict__ Alog0, const float* __restrict__ Alog1,
                          const float* __restrict__ Dp0,   const float* __restrict__ Dp1)
{
    int br = blockIdx.z, b = blockIdx.y;
    int tid = threadIdx.x;
    int n2 = tid & 7;
    int c = blockIdx.x & (NCH - 1);
    int d = (blockIdx.x >> 3) * 16 + (tid >> 3);

    const float* Alog = br ? Alog1 : Alog0;
    float2 Ac = *(const float2*)(Alog + d*Nst + 2*n2);
    float A0 = -__expf(Ac.x), A1 = -__expf(Ac.y);
    float Dv = (br ? Dp1 : Dp0)[d];

    const float* dt_p  = g_dt[br]  + (long)b*Lseq*DIN + d;
    const float* xc_p  = g_xc[br]  + (long)b*Lseq*DIN + d;
    const float* xdb_p = g_xdb[br] + (long)b*Lseq*XDBE;
    float*       y_p   = g_y[br]   + (long)b*Lseq*DIN + d;
    const float* z_p   = g_xz + (long)b*Lseq*(2*DIN) + DIN + d;

    // combine states of chunks 0..c-1 (exact linear-recurrence composition)
    float h0 = 0.f, h1 = 0.f;
    for (int j = 0; j < c; j++) {
        float2 s0 = g_cs[br][b][j][d][2*n2];
        float2 s1 = g_cs[br][b][j][d][2*n2 + 1];
        h0 = fmaf(s0.y, h0, s0.x);
        h1 = fmaf(s1.y, h1, s1.x);
    }

    int l0 = c * CS;
    int l1 = l0 + CS; if (l1 > Lseq) l1 = Lseq;

    for (int l = l0; l < l1; l++) {
        float dtv = dt_p[(long)l*DIN];
        float xcv = xc_p[(long)l*DIN];
        float2 Bv = *(const float2*)(xdb_p + l*XDBE + DTR + 2*n2);
        float2 Cv = *(const float2*)(xdb_p + l*XDBE + DTR + Nst + 2*n2);
        float e0 = __expf(dtv * A0);
        float e1 = __expf(dtv * A1);
        float dx = dtv * xcv;
        h0 = fmaf(e0, h0, dx * Bv.x);
        h1 = fmaf(e1, h1, dx * Bv.y);
        float p = h0 * Cv.x + h1 * Cv.y;
        p += __shfl_xor_sync(~0u, p, 4);
        p += __shfl_xor_sync(~0u, p, 2);
        p += __shfl_xor_sync(~0u, p, 1);
        if (n2 == 0) {
            int lz = br ? (Lseq - 1 - l) : l;
            float zv = z_p[(long)lz*(2*DIN)];
            y_p[(long)l*DIN] = (p + xcv * Dv) * silu_f(zv);
        }
    }
}

// ---------------- final: residual + LN at POS + cmd MLP ----------------
__global__ void final_kernel(const float* __restrict__ state_vec, const float* __restrict__ action,
                             const float* __restrict__ lnf_w, const float* __restrict__ lnf_b,
                             const float* __restrict__ cw1, const float* __restrict__ cb1,
                             const float* __restrict__ cw2, const float* __restrict__ cb2,
                             float* __restrict__ out)
{
    int b = blockIdx.x, t = threadIdx.x;    // 384 threads
    long off = ((long)b*Lseq + POS)*D + t;
    float v = g_hidden[off] + g_resid[off];

    float s = v, q = v*v;
    #pragma unroll
    for (int o = 16; o > 0; o >>= 1) {
        s += __shfl_xor_sync(~0u, s, o);
        q += __shfl_xor_sync(~0u, q, o);
    }
    __shared__ float rs[12], rq[12];
    __shared__ float s_mean, s_rstd;
    __shared__ float s_cmd[20];
    __shared__ float s_r1[D];
    int w = t >> 5, ln = t & 31;
    if (ln == 0) { rs[w] = s; rq[w] = q; }
    __syncthreads();
    if (t == 0) {
        float ss = 0.f, qq = 0.f;
        #pragma unroll
        for (int i = 0; i < 12; i++) { ss += rs[i]; qq += rq[i]; }
        float m = ss / D;
        s_mean = m;
        s_rstd = rsqrtf(qq / D - m*m + 1e-5f);
    }
    if (t < 16)      s_cmd[t] = state_vec[b*16 + t];
    else if (t < 20) s_cmd[t] = action[b*4 + t - 16];
    __syncthreads();

    float h = (v - s_mean) * s_rstd * lnf_w[t] + lnf_b[t];

    float r1 = cb1[t];
    #pragma unroll
    for (int j = 0; j < 20; j++) r1 = fmaf(s_cmd[j], cw1[t*20 + j], r1);
    s_r1[t] = fmaxf(r1, 0.0f);
    __syncthreads();

    float o2 = cb2[t];
    for (int e = 0; e < D; e++) o2 = fmaf(s_r1[e], cw2[t*D + e], o2);
    out[b*D + t] = h + o2;
}

// ---------------- host launcher ----------------
extern "C" void kernel_launch(void* const* d_in, const int* in_sizes, int n_in,
                              void* d_out, int out_size)
{
    const float* depth_seq = (const float*)d_in[0];
    const float* state_vec = (const float*)d_in[1];
    const float* action    = (const float*)d_in[2];
    const float* patch_w   = (const float*)d_in[3];
    const float* patch_b   = (const float*)d_in[4];
    const float* cls_token = (const float*)d_in[5];
    const float* pos_embed = (const float*)d_in[6];
    const float* ln_w      = (const float*)d_in[7];
    const float* ln_b      = (const float*)d_in[8];
    const float* in_proj_w = (const float*)d_in[9];
    const float* conv_w    = (const float*)d_in[10];
    const float* conv_b    = (const float*)d_in[11];
    const float* conv_wb   = (const float*)d_in[12];
    const float* conv_bb   = (const float*)d_in[13];
    const float* xproj_w   = (const float*)d_in[14];
    const float* xproj_wb  = (const float*)d_in[15];
    const float* dtproj_w  = (const float*)d_in[16];
    const float* dtproj_b  = (const float*)d_in[17];
    const float* dtproj_wb = (const float*)d_in[18];
    const float* dtproj_bb = (const float*)d_in[19];
    const float* A_log     = (const float*)d_in[20];
    const float* A_logb    = (const float*)d_in[21];
    const float* Dp        = (const float*)d_in[22];
    const float* Dpb       = (const float*)d_in[23];
    const float* out_w     = (const float*)d_in[24];
    const float* lnf_w     = (const float*)d_in[25];
    const float* lnf_b     = (const float*)d_in[26];
    const float* cw1       = (const float*)d_in[27];
    const float* cb1       = (const float*)d_in[28];
    const float* cw2       = (const float*)d_in[29];
    const float* cb2       = (const float*)d_in[30];
    float* out = (float*)d_out;

    float *p_xr, *p_tok, *p_hn, *p_xz, *p_xc, *p_xdb, *p_y0, *p_y1, *p_hidden, *p_dt;
    cudaGetSymbolAddress((void**)&p_xr,     g_xr);
    cudaGetSymbolAddress((void**)&p_tok,    g_tok);
    cudaGetSymbolAddress((void**)&p_hn,     g_hn);
    cudaGetSymbolAddress((void**)&p_xz,     g_xz);
    cudaGetSymbolAddress((void**)&p_xc,     g_xc);
    cudaGetSymbolAddress((void**)&p_xdb,    g_xdb);
    cudaGetSymbolAddress((void**)&p_hidden, g_hidden);
    cudaGetSymbolAddress((void**)&p_dt,     g_dt);
    {
        float* base;
        cudaGetSymbolAddress((void**)&base, g_y);
        p_y0 = base;
        p_y1 = base + (long)Bc*Lseq*DIN;
    }

    // 1) patchify + patch-embed GEMM (ks=1, bias)
    patchify_kernel<<<(Bc*NTOK*256 + 255)/256, 256>>>(depth_seq);
    {
        dim3 g(D/64, (Bc*NTOK)/64, 1);
        mma_gemm_kernel<<<g, 256>>>(p_xr, nullptr, patch_w, nullptr, patch_b, nullptr,
                                    p_tok, Bc*NTOK, D, 256, 256, D, 0, 0, 0, 1);
    }

    // 2) layers
    for (int i = 0; i < DEPTH; i++) {
        resln_kernel<<<(MSEQ + 3)/4, 128>>>(ln_w + i*D, ln_b + i*D, cls_token, pos_embed, i == 0);

        {   // in_proj: (1028,384) @ (1536,384)^T -> g_xz  (ks=1: big output, no atomics)
            dim3 g((2*DIN)/64, (MSEQ + 63)/64, 1);
            mma_gemm_kernel<<<g, 256>>>(p_hn, nullptr, in_proj_w + (long)i*2*DIN*D, nullptr,
                                        nullptr, nullptr, p_xz,
                                        MSEQ, 2*DIN, D, D, 2*DIN, 0, 0, 0, 1);
        }

        {   // conv + zero xdb/hidden rows for split-K accumulation
            dim3 g(MSEQ, 2);
            conv_kernel<<<g, 192>>>(conv_w + i*DIN*4, conv_b + i*DIN,
                                    conv_wb + i*DIN*4, conv_bb + i*DIN);
        }

        {   // xproj both branches, split-K x8 (tiny output -> cheap atomics)
            dim3 g(1, (MSEQ + 63)/64, 2*8);
            mma_gemm_kernel<<<g, 256>>>(p_xc, nullptr,
                                        xproj_w + (long)i*XDBE*DIN, xproj_wb + (long)i*XDBE*DIN,
                                        nullptr, nullptr, p_xdb,
                                        MSEQ, XDBE, DIN, DIN, XDBE,
                                        (long)Bc*Lseq*DIN, (long)Bc*Lseq*XDBE, 0, 8);
        }

        {   // dtproj both branches, softplus (ks=1)
            dim3 g(DIN/64, (MSEQ + 63)/64, 2);
            mma_gemm_kernel<<<g, 256>>>(p_xdb, nullptr,
                                        dtproj_w + (long)i*DIN*DTR, dtproj_wb + (long)i*DIN*DTR,
                                        dtproj_b + i*DIN, dtproj_bb + i*DIN, p_dt,
                                        MSEQ, DIN, DTR, XDBE, DIN,
                                        (long)Bc*Lseq*XDBE, (long)Bc*Lseq*DIN, 2, 1);
        }

        {   // chunked SSM scan: pass1 (per-chunk states) + pass2 (combine + emit y)
            dim3 g((DIN/16)*NCH, Bc, 2);
            ssm_pass1<<<g, 128>>>(A_log + (long)i*DIN*Nst, A_logb + (long)i*DIN*Nst);
            ssm_pass2<<<g, 128>>>(A_log + (long)i*DIN*Nst, A_logb + (long)i*DIN*Nst,
                                  Dp + i*DIN, Dpb + i*DIN);
        }

        {   // out_proj, combine fused (A = y0[m] + y1[flip(m)]), split-K x2
            dim3 g(D/64, (MSEQ + 63)/64, 2);
            mma_gemm_kernel<<<g, 256>>>(p_y0, p_y1, out_w + (long)i*D*DIN, nullptr,
                                        nullptr, nullptr, p_hidden,
                                        MSEQ, D, DIN, DIN, D, 0, 0, 0, 2);
        }
    }

    // 3) final LN at POS + command MLP
    final_kernel<<<Bc, D>>>(state_vec, action, lnf_w, lnf_b, cw1, cb1, cw2, cb2, out);
}